// round 1
// baseline (speedup 1.0000x reference)
#include <cuda_runtime.h>
#include <cstdint>

#define BATCH 4
#define SEQ   2048
#define DIM   768
#define HEADS 12
#define HDIM  64
#define SCALE_F 0.125f   // 64^-0.5

// Scratch (allocation-free rule: __device__ globals)
static __device__ float g_Q[(size_t)BATCH * HEADS * SEQ * HDIM];
static __device__ float g_K[(size_t)BATCH * HEADS * SEQ * HDIM];
static __device__ float g_V[(size_t)BATCH * HEADS * SEQ * HDIM];
static __device__ float g_O[(size_t)BATCH * SEQ * DIM];

// ---------------------------------------------------------------------------
// GEMM: C[M,N] = A[M,K] @ W[N,K]^T  (+ epilogue)
// MODE 0: QKV — scatter into g_Q (bias+scale), g_K, g_V (bias)
// MODE 1: proj — out = C + bias1
// 128x128 tile, BK=16, 256 threads, 8x8 per thread.
// ---------------------------------------------------------------------------
template <int MODE>
__global__ void __launch_bounds__(256) gemm_kernel(
    const float* __restrict__ A_in, const float* __restrict__ W,
    const float* __restrict__ bias1, const float* __restrict__ bias2,
    float* __restrict__ out, int M, int N, int K)
{
    __shared__ float As[16][128];
    __shared__ float Bs[16][128];

    const float* A = (MODE == 1) ? (const float*)g_O : A_in;

    const int tid = threadIdx.x;
    const int tx = tid & 15;
    const int ty = tid >> 4;
    const int m0 = blockIdx.y * 128;
    const int n0 = blockIdx.x * 128;

    float acc[8][8];
#pragma unroll
    for (int i = 0; i < 8; i++)
#pragma unroll
        for (int j = 0; j < 8; j++) acc[i][j] = 0.f;

    for (int k0 = 0; k0 < K; k0 += 16) {
#pragma unroll
        for (int i = 0; i < 2; i++) {
            int lin = i * 256 + tid;        // 0..511
            int row = lin >> 2;             // 0..127
            int c4  = (lin & 3) << 2;       // 0,4,8,12
            float4 va = *(const float4*)&A[(size_t)(m0 + row) * K + k0 + c4];
            As[c4 + 0][row] = va.x; As[c4 + 1][row] = va.y;
            As[c4 + 2][row] = va.z; As[c4 + 3][row] = va.w;
            float4 vb = *(const float4*)&W[(size_t)(n0 + row) * K + k0 + c4];
            Bs[c4 + 0][row] = vb.x; Bs[c4 + 1][row] = vb.y;
            Bs[c4 + 2][row] = vb.z; Bs[c4 + 3][row] = vb.w;
        }
        __syncthreads();
#pragma unroll
        for (int kk = 0; kk < 16; kk++) {
            float a[8], b[8];
            float4 a0 = *(const float4*)&As[kk][ty * 8];
            float4 a1 = *(const float4*)&As[kk][ty * 8 + 4];
            float4 b0 = *(const float4*)&Bs[kk][tx * 8];
            float4 b1 = *(const float4*)&Bs[kk][tx * 8 + 4];
            a[0]=a0.x; a[1]=a0.y; a[2]=a0.z; a[3]=a0.w;
            a[4]=a1.x; a[5]=a1.y; a[6]=a1.z; a[7]=a1.w;
            b[0]=b0.x; b[1]=b0.y; b[2]=b0.z; b[3]=b0.w;
            b[4]=b1.x; b[5]=b1.y; b[6]=b1.z; b[7]=b1.w;
#pragma unroll
            for (int i = 0; i < 8; i++)
#pragma unroll
                for (int j = 0; j < 8; j++)
                    acc[i][j] = fmaf(a[i], b[j], acc[i][j]);
        }
        __syncthreads();
    }

    // Epilogue
    if (MODE == 0) {
#pragma unroll
        for (int i = 0; i < 8; i++) {
            int m = m0 + ty * 8 + i;
            int b = m >> 11;           // /2048
            int t = m & 2047;
#pragma unroll
            for (int j4 = 0; j4 < 8; j4 += 4) {
                int n = n0 + tx * 8 + j4;
                int sec = n / DIM;          // 0=q,1=k,2=v (128-tile never crosses sec)
                int c = n - sec * DIM;
                int h = c >> 6;
                int d = c & 63;
                float4 v;
                v.x = acc[i][j4 + 0]; v.y = acc[i][j4 + 1];
                v.z = acc[i][j4 + 2]; v.w = acc[i][j4 + 3];
                float* dst;
                if (sec == 0) {
                    v.x = (v.x + bias1[c + 0]) * SCALE_F;
                    v.y = (v.y + bias1[c + 1]) * SCALE_F;
                    v.z = (v.z + bias1[c + 2]) * SCALE_F;
                    v.w = (v.w + bias1[c + 3]) * SCALE_F;
                    dst = g_Q;
                } else if (sec == 1) {
                    dst = g_K;
                } else {
                    v.x += bias2[c + 0]; v.y += bias2[c + 1];
                    v.z += bias2[c + 2]; v.w += bias2[c + 3];
                    dst = g_V;
                }
                size_t off = ((((size_t)b * HEADS + h) * SEQ + t) << 6) + d;
                *(float4*)&dst[off] = v;
            }
        }
    } else {
#pragma unroll
        for (int i = 0; i < 8; i++) {
            int m = m0 + ty * 8 + i;
#pragma unroll
            for (int j4 = 0; j4 < 8; j4 += 4) {
                int n = n0 + tx * 8 + j4;
                float4 v;
                v.x = acc[i][j4 + 0] + bias1[n + 0];
                v.y = acc[i][j4 + 1] + bias1[n + 1];
                v.z = acc[i][j4 + 2] + bias1[n + 2];
                v.w = acc[i][j4 + 3] + bias1[n + 3];
                *(float4*)&out[(size_t)m * N + n] = v;
            }
        }
    }
}

// ---------------------------------------------------------------------------
// Flash attention: one CTA per (b*h, qblock). Br=Bc=64, hd=64.
// Q pre-scaled by SCALE in the QKV epilogue.
// smem: Qs[64][64], KP[64][64] (K transposed [d][t], reused as P [i][j]),
//       Vs[64][64]  -> 48 KB exactly.
// Thread (tx,ty), 16x16 grid, owns S/O microtile rows ty*4..+3, cols tx*4..+3.
// ---------------------------------------------------------------------------
__global__ void __launch_bounds__(256) attn_kernel()
{
    __shared__ float Qs[64][64];
    __shared__ float KP[64][64];
    __shared__ float Vs[64][64];

    const int tid = threadIdx.x;
    const int tx = tid & 15;
    const int ty = tid >> 4;
    const int tx4 = tx * 4;
    const int ty4 = ty * 4;
    const int qb = blockIdx.x;
    const int bh = blockIdx.y;

    const float* Qp = g_Q + ((size_t)bh * SEQ + qb * 64) * HDIM;
    const float* Kp = g_K + (size_t)bh * SEQ * HDIM;
    const float* Vp = g_V + (size_t)bh * SEQ * HDIM;

    // Load Q tile (scaled already)
#pragma unroll
    for (int i = 0; i < 4; i++) {
        int lin = i * 256 + tid;          // 0..1023
        int row = lin >> 4;               // 0..63
        int c4  = (lin & 15) << 2;        // 0..60
        *(float4*)&Qs[row][c4] = *(const float4*)&Qp[(size_t)row * HDIM + c4];
    }

    float m_r[4], l_r[4], o[4][4];
#pragma unroll
    for (int r = 0; r < 4; r++) {
        m_r[r] = -1e30f;
        l_r[r] = 0.f;
#pragma unroll
        for (int c = 0; c < 4; c++) o[r][c] = 0.f;
    }

    for (int jt = 0; jt < SEQ / 64; jt++) {
        __syncthreads();  // prev PV readers done; also orders Qs on first iter
        // Load K (transposed into KP[d][t]) and V (normal) for this tile
#pragma unroll
        for (int i = 0; i < 4; i++) {
            int lin = i * 256 + tid;
            int row = lin >> 4;
            int c4  = (lin & 15) << 2;
            float4 kv = *(const float4*)&Kp[(size_t)(jt * 64 + row) * HDIM + c4];
            KP[c4 + 0][row] = kv.x; KP[c4 + 1][row] = kv.y;
            KP[c4 + 2][row] = kv.z; KP[c4 + 3][row] = kv.w;
            *(float4*)&Vs[row][c4] =
                *(const float4*)&Vp[(size_t)(jt * 64 + row) * HDIM + c4];
        }
        __syncthreads();

        // S = Q K^T  (16 elems per thread)
        float s[4][4];
#pragma unroll
        for (int r = 0; r < 4; r++)
#pragma unroll
            for (int c = 0; c < 4; c++) s[r][c] = 0.f;

#pragma unroll
        for (int d0 = 0; d0 < HDIM; d0 += 4) {
            float q[4][4], kf[4][4];
#pragma unroll
            for (int r = 0; r < 4; r++) {
                float4 t4 = *(const float4*)&Qs[ty4 + r][d0];
                q[r][0]=t4.x; q[r][1]=t4.y; q[r][2]=t4.z; q[r][3]=t4.w;
            }
#pragma unroll
            for (int u = 0; u < 4; u++) {
                float4 t4 = *(const float4*)&KP[d0 + u][tx4];
                kf[u][0]=t4.x; kf[u][1]=t4.y; kf[u][2]=t4.z; kf[u][3]=t4.w;
            }
#pragma unroll
            for (int r = 0; r < 4; r++)
#pragma unroll
                for (int c = 0; c < 4; c++)
#pragma unroll
                    for (int u = 0; u < 4; u++)
                        s[r][c] = fmaf(q[r][u], kf[u][c], s[r][c]);
        }

        // Online softmax update (row stats shared across 16 lanes of same ty)
#pragma unroll
        for (int r = 0; r < 4; r++) {
            float mx = fmaxf(fmaxf(s[r][0], s[r][1]), fmaxf(s[r][2], s[r][3]));
#pragma unroll
            for (int w = 1; w < 16; w <<= 1)
                mx = fmaxf(mx, __shfl_xor_sync(0xffffffffu, mx, w));
            float mnew = fmaxf(m_r[r], mx);
            float alpha = __expf(m_r[r] - mnew);
            m_r[r] = mnew;
            float sum = 0.f;
#pragma unroll
            for (int c = 0; c < 4; c++) {
                s[r][c] = __expf(s[r][c] - mnew);
                sum += s[r][c];
            }
#pragma unroll
            for (int w = 1; w < 16; w <<= 1)
                sum += __shfl_xor_sync(0xffffffffu, sum, w);
            l_r[r] = l_r[r] * alpha + sum;
#pragma unroll
            for (int c = 0; c < 4; c++) o[r][c] *= alpha;
        }

        __syncthreads();  // everyone finished reading KP (K data)
        // Store P into KP[i][j]
#pragma unroll
        for (int r = 0; r < 4; r++) {
            float4 p4;
            p4.x = s[r][0]; p4.y = s[r][1]; p4.z = s[r][2]; p4.w = s[r][3];
            *(float4*)&KP[ty4 + r][tx4] = p4;
        }
        __syncthreads();

        // O += P @ V
#pragma unroll
        for (int k0 = 0; k0 < 64; k0 += 4) {
            float p[4][4], vf[4][4];
#pragma unroll
            for (int r = 0; r < 4; r++) {
                float4 t4 = *(const float4*)&KP[ty4 + r][k0];
                p[r][0]=t4.x; p[r][1]=t4.y; p[r][2]=t4.z; p[r][3]=t4.w;
            }
#pragma unroll
            for (int u = 0; u < 4; u++) {
                float4 t4 = *(const float4*)&Vs[k0 + u][tx4];
                vf[u][0]=t4.x; vf[u][1]=t4.y; vf[u][2]=t4.z; vf[u][3]=t4.w;
            }
#pragma unroll
            for (int r = 0; r < 4; r++)
#pragma unroll
                for (int c = 0; c < 4; c++)
#pragma unroll
                    for (int u = 0; u < 4; u++)
                        o[r][c] = fmaf(p[r][u], vf[u][c], o[r][c]);
        }
    }

    // Normalize and write to g_O in [B, N, C] layout
    const int b = bh / HEADS;
    const int h = bh - b * HEADS;
#pragma unroll
    for (int r = 0; r < 4; r++) {
        float inv = 1.0f / l_r[r];
        int t = qb * 64 + ty4 + r;
        float4 w4;
        w4.x = o[r][0] * inv; w4.y = o[r][1] * inv;
        w4.z = o[r][2] * inv; w4.w = o[r][3] * inv;
        *(float4*)&g_O[((size_t)b * SEQ + t) * DIM + h * HDIM + tx4] = w4;
    }
}

// ---------------------------------------------------------------------------
extern "C" void kernel_launch(void* const* d_in, const int* in_sizes, int n_in,
                              void* d_out, int out_size)
{
    (void)in_sizes; (void)n_in; (void)out_size;
    const float* x      = (const float*)d_in[0];  // [4,2048,768]
    const float* qkv_w  = (const float*)d_in[1];  // [2304,768]
    const float* q_bias = (const float*)d_in[2];  // [768]
    const float* v_bias = (const float*)d_in[3];  // [768]
    const float* proj_w = (const float*)d_in[4];  // [768,768]
    const float* proj_b = (const float*)d_in[5];  // [768]
    float* out = (float*)d_out;                   // [4,2048,768]

    const int M = BATCH * SEQ;      // 8192

    // 1) QKV GEMM + bias/scale/scatter
    gemm_kernel<0><<<dim3((3 * DIM) / 128, M / 128), 256>>>(
        x, qkv_w, q_bias, v_bias, nullptr, M, 3 * DIM, DIM);

    // 2) Attention
    attn_kernel<<<dim3(SEQ / 64, BATCH * HEADS), 256>>>();

    // 3) Projection GEMM + bias
    gemm_kernel<1><<<dim3(DIM / 128, M / 128), 256>>>(
        nullptr, proj_w, proj_b, nullptr, out, M, DIM, DIM);
}

// round 3
// speedup vs baseline: 1.2553x; 1.2553x over previous
#include <cuda_runtime.h>
#include <cuda_bf16.h>
#include <cstdint>

#define BATCH 4
#define SEQ   2048
#define DIM   768
#define HEADS 12
#define HDIM  64
#define SCALE_F 0.125f   // 64^-0.5

// ---------------------------------------------------------------------------
// Scratch (allocation-free rule: __device__ globals)
// ---------------------------------------------------------------------------
static __device__ float g_Q[(size_t)BATCH * HEADS * SEQ * HDIM];
static __device__ float g_K[(size_t)BATCH * HEADS * SEQ * HDIM];
static __device__ float g_V[(size_t)BATCH * HEADS * SEQ * HDIM];
static __device__ float g_O[(size_t)BATCH * SEQ * DIM];

// bf16 hi/lo split operands
static __device__ __nv_bfloat16 g_xh[(size_t)BATCH * SEQ * DIM];
static __device__ __nv_bfloat16 g_xl[(size_t)BATCH * SEQ * DIM];
static __device__ __nv_bfloat16 g_wqh[(size_t)3 * DIM * DIM];
static __device__ __nv_bfloat16 g_wql[(size_t)3 * DIM * DIM];
static __device__ __nv_bfloat16 g_oh[(size_t)BATCH * SEQ * DIM];
static __device__ __nv_bfloat16 g_ol[(size_t)BATCH * SEQ * DIM];
static __device__ __nv_bfloat16 g_wph[(size_t)DIM * DIM];
static __device__ __nv_bfloat16 g_wpl[(size_t)DIM * DIM];

// ---------------------------------------------------------------------------
// helpers
// ---------------------------------------------------------------------------
__device__ __forceinline__ uint32_t smem_to_u32(const void* p) {
    uint32_t a;
    asm("{ .reg .u64 t; cvta.to.shared.u64 t, %1; cvt.u32.u64 %0, t; }"
        : "=r"(a) : "l"(p));
    return a;
}

__device__ __forceinline__ void cp_async16(uint32_t saddr, const void* gaddr) {
    asm volatile("cp.async.cg.shared.global [%0], [%1], 16;"
                 :: "r"(saddr), "l"(gaddr));
}
__device__ __forceinline__ void cp_commit() {
    asm volatile("cp.async.commit_group;");
}
__device__ __forceinline__ void cp_wait1() {
    asm volatile("cp.async.wait_group 1;" ::: "memory");
}
__device__ __forceinline__ void cp_wait0() {
    asm volatile("cp.async.wait_group 0;" ::: "memory");
}

__device__ __forceinline__ void ldsm_x4(uint32_t* r, uint32_t addr) {
    asm volatile("ldmatrix.sync.aligned.m8n8.x4.shared.b16 {%0,%1,%2,%3}, [%4];"
                 : "=r"(r[0]), "=r"(r[1]), "=r"(r[2]), "=r"(r[3]) : "r"(addr));
}

__device__ __forceinline__ void mma16816(float* d, const uint32_t* a,
                                         const uint32_t* b) {
    asm volatile(
        "mma.sync.aligned.m16n8k16.row.col.f32.bf16.bf16.f32 "
        "{%0,%1,%2,%3}, {%4,%5,%6,%7}, {%8,%9}, {%0,%1,%2,%3};"
        : "+f"(d[0]), "+f"(d[1]), "+f"(d[2]), "+f"(d[3])
        : "r"(a[0]), "r"(a[1]), "r"(a[2]), "r"(a[3]), "r"(b[0]), "r"(b[1]));
}

// ---------------------------------------------------------------------------
// fp32 -> bf16 hi/lo split
// WHICH: 0=x, 1=qkv_w, 2=proj_w, 3=g_O
// ---------------------------------------------------------------------------
template <int WHICH>
__global__ void convert_split_exact(const float* __restrict__ in_param, int n2)
{
    __nv_bfloat162* hi;
    __nv_bfloat162* lo;
    const float* in = in_param;
    if (WHICH == 0) { hi = (__nv_bfloat162*)g_xh;  lo = (__nv_bfloat162*)g_xl; }
    if (WHICH == 1) { hi = (__nv_bfloat162*)g_wqh; lo = (__nv_bfloat162*)g_wql; }
    if (WHICH == 2) { hi = (__nv_bfloat162*)g_wph; lo = (__nv_bfloat162*)g_wpl; }
    if (WHICH == 3) { hi = (__nv_bfloat162*)g_oh;  lo = (__nv_bfloat162*)g_ol; in = g_O; }

    int i = blockIdx.x * blockDim.x + threadIdx.x;
    if (i < n2) {
        float2 v = ((const float2*)in)[i];
        __nv_bfloat16 hx = __float2bfloat16_rn(v.x);
        __nv_bfloat16 hy = __float2bfloat16_rn(v.y);
        __nv_bfloat162 h; h.x = hx; h.y = hy;
        hi[i] = h;
        float rx = v.x - __bfloat162float(hx);
        float ry = v.y - __bfloat162float(hy);
        __nv_bfloat162 l;
        l.x = __float2bfloat16_rn(rx); l.y = __float2bfloat16_rn(ry);
        lo[i] = l;
    }
}

// ---------------------------------------------------------------------------
// HMMA GEMM: C[M,N] = A[M,768] @ W[N,768]^T via bf16 hi/lo 3-term split.
// CTA: 128x128 tile, BK=32, 256 threads = 8 warps (2M x 4N), warp tile 64x32.
// Double-buffered cp.async, ldmatrix frags, 80B smem row pitch (conflict-free).
// MODE 0: A=x split, W=qkv split, epilogue scatters to g_Q/g_K/g_V.
// MODE 1: A=g_O split, W=proj split, epilogue writes out + bias.
// smem: 4 operands x 2 stages x 128 rows x 80B = 81920 B.
// ---------------------------------------------------------------------------
#define PITCH_B 80
#define STAGE_B (128 * PITCH_B)          // 10240
static constexpr int GEMM_SMEM = 8 * STAGE_B;  // 81920

template <int MODE>
__global__ void __launch_bounds__(256) gemm_mma(
    const float* __restrict__ bias1, const float* __restrict__ bias2,
    float* __restrict__ out)
{
    constexpr int K = DIM;            // 768
    constexpr int NST = K / 32;       // 24

    extern __shared__ char smem[];
    const uint32_t sbase = smem_to_u32(smem);

    const __nv_bfloat16* Ah = (MODE == 0) ? g_xh : g_oh;
    const __nv_bfloat16* Al = (MODE == 0) ? g_xl : g_ol;
    const __nv_bfloat16* Wh = (MODE == 0) ? g_wqh : g_wph;
    const __nv_bfloat16* Wl = (MODE == 0) ? g_wql : g_wpl;
    const __nv_bfloat16* gsrc[4] = { Ah, Al, Wh, Wl };

    const int tid  = threadIdx.x;
    const int lane = tid & 31;
    const int wid  = tid >> 5;
    const int mw   = wid >> 2;        // 0..1
    const int nw   = wid & 3;         // 0..3
    const int m0   = blockIdx.y * 128;
    const int n0   = blockIdx.x * 128;

    // ldmatrix per-lane address components
    const int T   = lane >> 3;
    const int la  = lane & 7;
    const int arow = ((T & 1) << 3) + la;   // A: intra-atom row
    const int akb  = (T >> 1) << 3;         // A: k offset
    const int brow = ((T >> 1) << 3) + la;  // B: intra-pair row
    const int bkb  = (T & 1) << 3;          // B: k offset

    float acc[4][4][4];
#pragma unroll
    for (int i = 0; i < 4; i++)
#pragma unroll
        for (int j = 0; j < 4; j++)
#pragma unroll
            for (int k = 0; k < 4; k++) acc[i][j][k] = 0.f;

    // ---- cp.async tile loader: stage s (buffer s&1), k-offset kq ----
    // 2048 16B-chunks per stage: op(4) x row(128) x unit(4)
    auto load_stage = [&](int s, int kq) {
#pragma unroll
        for (int i = 0; i < 8; i++) {
            int c   = i * 256 + tid;
            int op  = c >> 9;
            int rem = c & 511;
            int row = rem >> 2;
            int u   = rem & 3;
            int grow = (op < 2) ? (m0 + row) : (n0 + row);
            const __nv_bfloat16* g = gsrc[op] + (size_t)grow * K + kq + u * 8;
            uint32_t d = sbase + (uint32_t)(((op << 1) + (s & 1)) * STAGE_B
                                            + row * PITCH_B + u * 16);
            cp_async16(d, g);
        }
        cp_commit();
    };

    load_stage(0, 0);
    load_stage(1, 32);

    for (int kb = 0; kb < NST; kb++) {
        if (kb + 1 < NST) cp_wait1(); else cp_wait0();
        __syncthreads();

        const int s = kb & 1;
        const uint32_t bAh = sbase + (uint32_t)((0 * 2 + s) * STAGE_B);
        const uint32_t bAl = sbase + (uint32_t)((1 * 2 + s) * STAGE_B);
        const uint32_t bWh = sbase + (uint32_t)((2 * 2 + s) * STAGE_B);
        const uint32_t bWl = sbase + (uint32_t)((3 * 2 + s) * STAGE_B);

#pragma unroll
        for (int kk = 0; kk < 2; kk++) {
            uint32_t ah[4][4], al[4][4], wh[2][4], wl[2][4];
#pragma unroll
            for (int ma = 0; ma < 4; ma++) {
                uint32_t off = (uint32_t)((mw * 64 + ma * 16 + arow) * PITCH_B
                                          + (kk * 16 + akb) * 2);
                ldsm_x4(ah[ma], bAh + off);
                ldsm_x4(al[ma], bAl + off);
            }
#pragma unroll
            for (int nb = 0; nb < 2; nb++) {
                uint32_t off = (uint32_t)((nw * 32 + nb * 16 + brow) * PITCH_B
                                          + (kk * 16 + bkb) * 2);
                ldsm_x4(wh[nb], bWh + off);
                ldsm_x4(wl[nb], bWl + off);
            }
            // wh[nb] regs: {b0,b1} = atom nb*2, {b2,b3} = atom nb*2+1
#pragma unroll
            for (int ma = 0; ma < 4; ma++)
#pragma unroll
                for (int na = 0; na < 4; na++) {
                    const uint32_t* bh = &wh[na >> 1][(na & 1) * 2];
                    const uint32_t* bl = &wl[na >> 1][(na & 1) * 2];
                    mma16816(acc[ma][na], ah[ma], bh);
                    mma16816(acc[ma][na], ah[ma], bl);
                    mma16816(acc[ma][na], al[ma], bh);
                }
        }
        __syncthreads();
        if (kb + 2 < NST) load_stage(kb + 2, (kb + 2) * 32);
    }

    // ---- epilogue (registers -> global) ----
    const int qrow = lane >> 2;
    const int qcol = (lane & 3) << 1;

    if (MODE == 0) {
        const int sec = blockIdx.x / 6;            // 0=q 1=k 2=v
        const int nl0 = (blockIdx.x % 6) * 128;
        float* dst = (sec == 0) ? g_Q : ((sec == 1) ? g_K : g_V);
#pragma unroll
        for (int na = 0; na < 4; na++) {
            const int c = nl0 + nw * 32 + na * 8 + qcol;   // 0..767
            const int h = c >> 6, d = c & 63;
            float bx = 0.f, by = 0.f;
            if (sec == 0) { bx = bias1[c]; by = bias1[c + 1]; }
            if (sec == 2) { bx = bias2[c]; by = bias2[c + 1]; }
#pragma unroll
            for (int ma = 0; ma < 4; ma++) {
                const int mr = m0 + mw * 64 + ma * 16 + qrow;
#pragma unroll
                for (int half = 0; half < 2; half++) {
                    int m = mr + half * 8;
                    int b = m >> 11, t = m & 2047;
                    float2 v;
                    v.x = acc[ma][na][half * 2 + 0] + bx;
                    v.y = acc[ma][na][half * 2 + 1] + by;
                    if (sec == 0) { v.x *= SCALE_F; v.y *= SCALE_F; }
                    size_t off = ((((size_t)b * HEADS + h) * SEQ + t) << 6) + d;
                    *(float2*)&dst[off] = v;
                }
            }
        }
    } else {
#pragma unroll
        for (int na = 0; na < 4; na++) {
            const int n = n0 + nw * 32 + na * 8 + qcol;
            const float bx = bias1[n], by = bias1[n + 1];
#pragma unroll
            for (int ma = 0; ma < 4; ma++) {
                const int mr = m0 + mw * 64 + ma * 16 + qrow;
#pragma unroll
                for (int half = 0; half < 2; half++) {
                    int m = mr + half * 8;
                    float2 v;
                    v.x = acc[ma][na][half * 2 + 0] + bx;
                    v.y = acc[ma][na][half * 2 + 1] + by;
                    *(float2*)&out[(size_t)m * DIM + n] = v;
                }
            }
        }
    }
}

// ---------------------------------------------------------------------------
// Flash attention (fp32 SIMT — round-4 target)
// ---------------------------------------------------------------------------
__global__ void __launch_bounds__(256) attn_kernel()
{
    __shared__ float Qs[64][64];
    __shared__ float KP[64][64];
    __shared__ float Vs[64][64];

    const int tid = threadIdx.x;
    const int tx = tid & 15;
    const int ty = tid >> 4;
    const int tx4 = tx * 4;
    const int ty4 = ty * 4;
    const int qb = blockIdx.x;
    const int bh = blockIdx.y;

    const float* Qp = g_Q + ((size_t)bh * SEQ + qb * 64) * HDIM;
    const float* Kp = g_K + (size_t)bh * SEQ * HDIM;
    const float* Vp = g_V + (size_t)bh * SEQ * HDIM;

#pragma unroll
    for (int i = 0; i < 4; i++) {
        int lin = i * 256 + tid;
        int row = lin >> 4;
        int c4  = (lin & 15) << 2;
        *(float4*)&Qs[row][c4] = *(const float4*)&Qp[(size_t)row * HDIM + c4];
    }

    float m_r[4], l_r[4], o[4][4];
#pragma unroll
    for (int r = 0; r < 4; r++) {
        m_r[r] = -1e30f;
        l_r[r] = 0.f;
#pragma unroll
        for (int c = 0; c < 4; c++) o[r][c] = 0.f;
    }

    for (int jt = 0; jt < SEQ / 64; jt++) {
        __syncthreads();
#pragma unroll
        for (int i = 0; i < 4; i++) {
            int lin = i * 256 + tid;
            int row = lin >> 4;
            int c4  = (lin & 15) << 2;
            float4 kv = *(const float4*)&Kp[(size_t)(jt * 64 + row) * HDIM + c4];
            KP[c4 + 0][row] = kv.x; KP[c4 + 1][row] = kv.y;
            KP[c4 + 2][row] = kv.z; KP[c4 + 3][row] = kv.w;
            *(float4*)&Vs[row][c4] =
                *(const float4*)&Vp[(size_t)(jt * 64 + row) * HDIM + c4];
        }
        __syncthreads();

        float s[4][4];
#pragma unroll
        for (int r = 0; r < 4; r++)
#pragma unroll
            for (int c = 0; c < 4; c++) s[r][c] = 0.f;

#pragma unroll
        for (int d0 = 0; d0 < HDIM; d0 += 4) {
            float q[4][4], kf[4][4];
#pragma unroll
            for (int r = 0; r < 4; r++) {
                float4 t4 = *(const float4*)&Qs[ty4 + r][d0];
                q[r][0]=t4.x; q[r][1]=t4.y; q[r][2]=t4.z; q[r][3]=t4.w;
            }
#pragma unroll
            for (int u = 0; u < 4; u++) {
                float4 t4 = *(const float4*)&KP[d0 + u][tx4];
                kf[u][0]=t4.x; kf[u][1]=t4.y; kf[u][2]=t4.z; kf[u][3]=t4.w;
            }
#pragma unroll
            for (int r = 0; r < 4; r++)
#pragma unroll
                for (int c = 0; c < 4; c++)
#pragma unroll
                    for (int u = 0; u < 4; u++)
                        s[r][c] = fmaf(q[r][u], kf[u][c], s[r][c]);
        }

#pragma unroll
        for (int r = 0; r < 4; r++) {
            float mx = fmaxf(fmaxf(s[r][0], s[r][1]), fmaxf(s[r][2], s[r][3]));
#pragma unroll
            for (int w = 1; w < 16; w <<= 1)
                mx = fmaxf(mx, __shfl_xor_sync(0xffffffffu, mx, w));
            float mnew = fmaxf(m_r[r], mx);
            float alpha = __expf(m_r[r] - mnew);
            m_r[r] = mnew;
            float sum = 0.f;
#pragma unroll
            for (int c = 0; c < 4; c++) {
                s[r][c] = __expf(s[r][c] - mnew);
                sum += s[r][c];
            }
#pragma unroll
            for (int w = 1; w < 16; w <<= 1)
                sum += __shfl_xor_sync(0xffffffffu, sum, w);
            l_r[r] = l_r[r] * alpha + sum;
#pragma unroll
            for (int c = 0; c < 4; c++) o[r][c] *= alpha;
        }

        __syncthreads();
#pragma unroll
        for (int r = 0; r < 4; r++) {
            float4 p4;
            p4.x = s[r][0]; p4.y = s[r][1]; p4.z = s[r][2]; p4.w = s[r][3];
            *(float4*)&KP[ty4 + r][tx4] = p4;
        }
        __syncthreads();

#pragma unroll
        for (int k0 = 0; k0 < 64; k0 += 4) {
            float p[4][4], vf[4][4];
#pragma unroll
            for (int r = 0; r < 4; r++) {
                float4 t4 = *(const float4*)&KP[ty4 + r][k0];
                p[r][0]=t4.x; p[r][1]=t4.y; p[r][2]=t4.z; p[r][3]=t4.w;
            }
#pragma unroll
            for (int u = 0; u < 4; u++) {
                float4 t4 = *(const float4*)&Vs[k0 + u][tx4];
                vf[u][0]=t4.x; vf[u][1]=t4.y; vf[u][2]=t4.z; vf[u][3]=t4.w;
            }
#pragma unroll
            for (int r = 0; r < 4; r++)
#pragma unroll
                for (int c = 0; c < 4; c++)
#pragma unroll
                    for (int u = 0; u < 4; u++)
                        o[r][c] = fmaf(p[r][u], vf[u][c], o[r][c]);
        }
    }

    const int b = bh / HEADS;
    const int h = bh - b * HEADS;
#pragma unroll
    for (int r = 0; r < 4; r++) {
        float inv = 1.0f / l_r[r];
        int t = qb * 64 + ty4 + r;
        float4 w4;
        w4.x = o[r][0] * inv; w4.y = o[r][1] * inv;
        w4.z = o[r][2] * inv; w4.w = o[r][3] * inv;
        *(float4*)&g_O[((size_t)b * SEQ + t) * DIM + h * HDIM + tx4] = w4;
    }
}

// ---------------------------------------------------------------------------
extern "C" void kernel_launch(void* const* d_in, const int* in_sizes, int n_in,
                              void* d_out, int out_size)
{
    (void)in_sizes; (void)n_in; (void)out_size;
    const float* x      = (const float*)d_in[0];
    const float* qkv_w  = (const float*)d_in[1];
    const float* q_bias = (const float*)d_in[2];
    const float* v_bias = (const float*)d_in[3];
    const float* proj_w = (const float*)d_in[4];
    const float* proj_b = (const float*)d_in[5];
    float* out = (float*)d_out;

    cudaFuncSetAttribute(gemm_mma<0>, cudaFuncAttributeMaxDynamicSharedMemorySize, GEMM_SMEM);
    cudaFuncSetAttribute(gemm_mma<1>, cudaFuncAttributeMaxDynamicSharedMemorySize, GEMM_SMEM);

    // 0) split fp32 -> bf16 hi/lo
    convert_split_exact<0><<<(BATCH * SEQ * DIM / 2 + 255) / 256, 256>>>(x, BATCH * SEQ * DIM / 2);
    convert_split_exact<1><<<(3 * DIM * DIM / 2 + 255) / 256, 256>>>(qkv_w, 3 * DIM * DIM / 2);
    convert_split_exact<2><<<(DIM * DIM / 2 + 255) / 256, 256>>>(proj_w, DIM * DIM / 2);

    // 1) QKV GEMM (HMMA) + bias/scale/scatter
    gemm_mma<0><<<dim3(3 * DIM / 128, BATCH * SEQ / 128), 256, GEMM_SMEM>>>(
        q_bias, v_bias, nullptr);

    // 2) Attention (fp32 SIMT)
    attn_kernel<<<dim3(SEQ / 64, BATCH * HEADS), 256>>>();

    // 3) split attention output, projection GEMM (HMMA) + bias
    convert_split_exact<3><<<(BATCH * SEQ * DIM / 2 + 255) / 256, 256>>>(nullptr, BATCH * SEQ * DIM / 2);
    gemm_mma<1><<<dim3(DIM / 128, BATCH * SEQ / 128), 256, GEMM_SMEM>>>(
        proj_b, nullptr, out);
}

// round 4
// speedup vs baseline: 3.6532x; 2.9102x over previous
#include <cuda_runtime.h>
#include <cuda_bf16.h>
#include <cuda_fp16.h>
#include <cstdint>

#define BATCH 4
#define SEQ   2048
#define DIM   768
#define HEADS 12
#define HDIM  64
#define SCALE_F 0.125f   // 64^-0.5
#define LOG2E_F 1.4426950408889634f

// ---------------------------------------------------------------------------
// Scratch (allocation-free rule: __device__ globals)
// ---------------------------------------------------------------------------
static __device__ __nv_bfloat16 g_Qh[(size_t)BATCH * HEADS * SEQ * HDIM];
static __device__ __nv_bfloat16 g_Ql[(size_t)BATCH * HEADS * SEQ * HDIM];
static __device__ __nv_bfloat16 g_Kh[(size_t)BATCH * HEADS * SEQ * HDIM];
static __device__ __nv_bfloat16 g_Kl[(size_t)BATCH * HEADS * SEQ * HDIM];
static __device__ __half        g_Vh[(size_t)BATCH * HEADS * SEQ * HDIM];

static __device__ __nv_bfloat16 g_xh[(size_t)BATCH * SEQ * DIM];
static __device__ __nv_bfloat16 g_xl[(size_t)BATCH * SEQ * DIM];
static __device__ __nv_bfloat16 g_wqh[(size_t)3 * DIM * DIM];
static __device__ __nv_bfloat16 g_wql[(size_t)3 * DIM * DIM];
static __device__ __nv_bfloat16 g_oh[(size_t)BATCH * SEQ * DIM];
static __device__ __nv_bfloat16 g_ol[(size_t)BATCH * SEQ * DIM];
static __device__ __nv_bfloat16 g_wph[(size_t)DIM * DIM];
static __device__ __nv_bfloat16 g_wpl[(size_t)DIM * DIM];

// ---------------------------------------------------------------------------
// helpers
// ---------------------------------------------------------------------------
__device__ __forceinline__ uint32_t smem_to_u32(const void* p) {
    uint32_t a;
    asm("{ .reg .u64 t; cvta.to.shared.u64 t, %1; cvt.u32.u64 %0, t; }"
        : "=r"(a) : "l"(p));
    return a;
}
__device__ __forceinline__ void cp_async16(uint32_t saddr, const void* gaddr) {
    asm volatile("cp.async.cg.shared.global [%0], [%1], 16;"
                 :: "r"(saddr), "l"(gaddr));
}
__device__ __forceinline__ void cp_commit() {
    asm volatile("cp.async.commit_group;");
}
__device__ __forceinline__ void cp_wait1() {
    asm volatile("cp.async.wait_group 1;" ::: "memory");
}
__device__ __forceinline__ void cp_wait0() {
    asm volatile("cp.async.wait_group 0;" ::: "memory");
}
__device__ __forceinline__ void ldsm_x4(uint32_t* r, uint32_t addr) {
    asm volatile("ldmatrix.sync.aligned.m8n8.x4.shared.b16 {%0,%1,%2,%3}, [%4];"
                 : "=r"(r[0]), "=r"(r[1]), "=r"(r[2]), "=r"(r[3]) : "r"(addr));
}
__device__ __forceinline__ void ldsm_x4_t(uint32_t* r, uint32_t addr) {
    asm volatile("ldmatrix.sync.aligned.m8n8.x4.trans.shared.b16 {%0,%1,%2,%3}, [%4];"
                 : "=r"(r[0]), "=r"(r[1]), "=r"(r[2]), "=r"(r[3]) : "r"(addr));
}
__device__ __forceinline__ void mma_bf16(float* d, const uint32_t* a,
                                         const uint32_t* b) {
    asm volatile(
        "mma.sync.aligned.m16n8k16.row.col.f32.bf16.bf16.f32 "
        "{%0,%1,%2,%3}, {%4,%5,%6,%7}, {%8,%9}, {%0,%1,%2,%3};"
        : "+f"(d[0]), "+f"(d[1]), "+f"(d[2]), "+f"(d[3])
        : "r"(a[0]), "r"(a[1]), "r"(a[2]), "r"(a[3]), "r"(b[0]), "r"(b[1]));
}
__device__ __forceinline__ void mma_f16(float* d, const uint32_t* a,
                                        const uint32_t* b) {
    asm volatile(
        "mma.sync.aligned.m16n8k16.row.col.f32.f16.f16.f32 "
        "{%0,%1,%2,%3}, {%4,%5,%6,%7}, {%8,%9}, {%0,%1,%2,%3};"
        : "+f"(d[0]), "+f"(d[1]), "+f"(d[2]), "+f"(d[3])
        : "r"(a[0]), "r"(a[1]), "r"(a[2]), "r"(a[3]), "r"(b[0]), "r"(b[1]));
}
__device__ __forceinline__ float ex2f(float x) {
    float r;
    asm("ex2.approx.f32 %0, %1;" : "=f"(r) : "f"(x));
    return r;
}
__device__ __forceinline__ uint32_t pack_f16x2(float lo, float hi) {
    uint32_t r;
    asm("cvt.rn.f16x2.f32 %0, %1, %2;" : "=r"(r) : "f"(hi), "f"(lo));
    return r;
}

// ---------------------------------------------------------------------------
// fp32 -> bf16 hi/lo split  (0=x, 1=qkv_w, 2=proj_w)
// ---------------------------------------------------------------------------
template <int WHICH>
__global__ void convert_split_exact(const float* __restrict__ in, int n2)
{
    __nv_bfloat162* hi;
    __nv_bfloat162* lo;
    if (WHICH == 0) { hi = (__nv_bfloat162*)g_xh;  lo = (__nv_bfloat162*)g_xl; }
    if (WHICH == 1) { hi = (__nv_bfloat162*)g_wqh; lo = (__nv_bfloat162*)g_wql; }
    if (WHICH == 2) { hi = (__nv_bfloat162*)g_wph; lo = (__nv_bfloat162*)g_wpl; }

    int i = blockIdx.x * blockDim.x + threadIdx.x;
    if (i < n2) {
        float2 v = ((const float2*)in)[i];
        __nv_bfloat16 hx = __float2bfloat16_rn(v.x);
        __nv_bfloat16 hy = __float2bfloat16_rn(v.y);
        __nv_bfloat162 h; h.x = hx; h.y = hy;
        hi[i] = h;
        __nv_bfloat162 l;
        l.x = __float2bfloat16_rn(v.x - __bfloat162float(hx));
        l.y = __float2bfloat16_rn(v.y - __bfloat162float(hy));
        lo[i] = l;
    }
}

// ---------------------------------------------------------------------------
// HMMA GEMM (as round 3). MODE 0 epilogue now writes split Q/K (bf16) + V f16.
// ---------------------------------------------------------------------------
#define PITCH_B 80
#define STAGE_B (128 * PITCH_B)
static constexpr int GEMM_SMEM = 8 * STAGE_B;  // 81920

template <int MODE>
__global__ void __launch_bounds__(256) gemm_mma(
    const float* __restrict__ bias1, const float* __restrict__ bias2,
    float* __restrict__ out)
{
    constexpr int K = DIM;
    constexpr int NST = K / 32;       // 24

    extern __shared__ char smem[];
    const uint32_t sbase = smem_to_u32(smem);

    const __nv_bfloat16* Ah = (MODE == 0) ? g_xh : g_oh;
    const __nv_bfloat16* Al = (MODE == 0) ? g_xl : g_ol;
    const __nv_bfloat16* Wh = (MODE == 0) ? g_wqh : g_wph;
    const __nv_bfloat16* Wl = (MODE == 0) ? g_wql : g_wpl;
    const __nv_bfloat16* gsrc[4] = { Ah, Al, Wh, Wl };

    const int tid  = threadIdx.x;
    const int lane = tid & 31;
    const int wid  = tid >> 5;
    const int mw   = wid >> 2;
    const int nw   = wid & 3;
    const int m0   = blockIdx.y * 128;
    const int n0   = blockIdx.x * 128;

    const int T   = lane >> 3;
    const int la  = lane & 7;
    const int arow = ((T & 1) << 3) + la;
    const int akb  = (T >> 1) << 3;
    const int brow = ((T >> 1) << 3) + la;
    const int bkb  = (T & 1) << 3;

    float acc[4][4][4];
#pragma unroll
    for (int i = 0; i < 4; i++)
#pragma unroll
        for (int j = 0; j < 4; j++)
#pragma unroll
            for (int k = 0; k < 4; k++) acc[i][j][k] = 0.f;

    auto load_stage = [&](int s, int kq) {
#pragma unroll
        for (int i = 0; i < 8; i++) {
            int c   = i * 256 + tid;
            int op  = c >> 9;
            int rem = c & 511;
            int row = rem >> 2;
            int u   = rem & 3;
            int grow = (op < 2) ? (m0 + row) : (n0 + row);
            const __nv_bfloat16* g = gsrc[op] + (size_t)grow * K + kq + u * 8;
            uint32_t d = sbase + (uint32_t)(((op << 1) + (s & 1)) * STAGE_B
                                            + row * PITCH_B + u * 16);
            cp_async16(d, g);
        }
        cp_commit();
    };

    load_stage(0, 0);
    load_stage(1, 32);

    for (int kb = 0; kb < NST; kb++) {
        if (kb + 1 < NST) cp_wait1(); else cp_wait0();
        __syncthreads();

        const int s = kb & 1;
        const uint32_t bAh = sbase + (uint32_t)((0 * 2 + s) * STAGE_B);
        const uint32_t bAl = sbase + (uint32_t)((1 * 2 + s) * STAGE_B);
        const uint32_t bWh = sbase + (uint32_t)((2 * 2 + s) * STAGE_B);
        const uint32_t bWl = sbase + (uint32_t)((3 * 2 + s) * STAGE_B);

#pragma unroll
        for (int kk = 0; kk < 2; kk++) {
            uint32_t ah[4][4], al[4][4], wh[2][4], wl[2][4];
#pragma unroll
            for (int ma = 0; ma < 4; ma++) {
                uint32_t off = (uint32_t)((mw * 64 + ma * 16 + arow) * PITCH_B
                                          + (kk * 16 + akb) * 2);
                ldsm_x4(ah[ma], bAh + off);
                ldsm_x4(al[ma], bAl + off);
            }
#pragma unroll
            for (int nb = 0; nb < 2; nb++) {
                uint32_t off = (uint32_t)((nw * 32 + nb * 16 + brow) * PITCH_B
                                          + (kk * 16 + bkb) * 2);
                ldsm_x4(wh[nb], bWh + off);
                ldsm_x4(wl[nb], bWl + off);
            }
#pragma unroll
            for (int ma = 0; ma < 4; ma++)
#pragma unroll
                for (int na = 0; na < 4; na++) {
                    const uint32_t* bh = &wh[na >> 1][(na & 1) * 2];
                    const uint32_t* bl = &wl[na >> 1][(na & 1) * 2];
                    mma_bf16(acc[ma][na], ah[ma], bh);
                    mma_bf16(acc[ma][na], ah[ma], bl);
                    mma_bf16(acc[ma][na], al[ma], bh);
                }
        }
        __syncthreads();
        if (kb + 2 < NST) load_stage(kb + 2, (kb + 2) * 32);
    }

    const int qrow = lane >> 2;
    const int qcol = (lane & 3) << 1;

    if (MODE == 0) {
        const int sec = blockIdx.x / 6;            // 0=q 1=k 2=v
        const int nl0 = (blockIdx.x % 6) * 128;
#pragma unroll
        for (int na = 0; na < 4; na++) {
            const int c = nl0 + nw * 32 + na * 8 + qcol;   // 0..767
            const int h = c >> 6, d = c & 63;
            float bx = 0.f, by = 0.f;
            if (sec == 0) { bx = bias1[c]; by = bias1[c + 1]; }
            if (sec == 2) { bx = bias2[c]; by = bias2[c + 1]; }
#pragma unroll
            for (int ma = 0; ma < 4; ma++) {
                const int mr = m0 + mw * 64 + ma * 16 + qrow;
#pragma unroll
                for (int half = 0; half < 2; half++) {
                    int m = mr + half * 8;
                    int b = m >> 11, t = m & 2047;
                    float vx = acc[ma][na][half * 2 + 0] + bx;
                    float vy = acc[ma][na][half * 2 + 1] + by;
                    size_t off = ((((size_t)b * HEADS + h) * SEQ + t) << 6) + d;
                    if (sec == 2) {
                        *(__half2*)&g_Vh[off] = __floats2half2_rn(vx, vy);
                    } else {
                        if (sec == 0) { vx *= SCALE_F; vy *= SCALE_F; }
                        __nv_bfloat16 hx = __float2bfloat16_rn(vx);
                        __nv_bfloat16 hy = __float2bfloat16_rn(vy);
                        __nv_bfloat162 hv; hv.x = hx; hv.y = hy;
                        __nv_bfloat162 lv;
                        lv.x = __float2bfloat16_rn(vx - __bfloat162float(hx));
                        lv.y = __float2bfloat16_rn(vy - __bfloat162float(hy));
                        if (sec == 0) {
                            *(__nv_bfloat162*)&g_Qh[off] = hv;
                            *(__nv_bfloat162*)&g_Ql[off] = lv;
                        } else {
                            *(__nv_bfloat162*)&g_Kh[off] = hv;
                            *(__nv_bfloat162*)&g_Kl[off] = lv;
                        }
                    }
                }
            }
        }
    } else {
#pragma unroll
        for (int na = 0; na < 4; na++) {
            const int n = n0 + nw * 32 + na * 8 + qcol;
            const float bx = bias1[n], by = bias1[n + 1];
#pragma unroll
            for (int ma = 0; ma < 4; ma++) {
                const int mr = m0 + mw * 64 + ma * 16 + qrow;
#pragma unroll
                for (int half = 0; half < 2; half++) {
                    int m = mr + half * 8;
                    float2 v;
                    v.x = acc[ma][na][half * 2 + 0] + bx;
                    v.y = acc[ma][na][half * 2 + 1] + by;
                    *(float2*)&out[(size_t)m * DIM + n] = v;
                }
            }
        }
    }
}

// ---------------------------------------------------------------------------
// HMMA flash attention. Br=128, Bc=64, 256 threads = 8 warps (each m16).
// QK: bf16 hi/lo 3-term; softmax in regs; PV: fp16 (P converted in-register).
// smem: 2 stages x (Kh,Kl,V) tiles, 64 rows x 144B pitch each; Q staged first.
// ---------------------------------------------------------------------------
#define APITCH 144
#define ATILE_B (64 * APITCH)            // 9216
static constexpr int ATTN_SMEM = 6 * ATILE_B;   // 55296

__global__ void __launch_bounds__(256) attn_mma()
{
    extern __shared__ char smem[];
    const uint32_t sbase = smem_to_u32(smem);

    const int tid  = threadIdx.x;
    const int lane = tid & 31;
    const int w    = tid >> 5;
    const int qb   = blockIdx.x;      // 0..15
    const int bh   = blockIdx.y;      // 0..47

    const int T  = lane >> 3;
    const int la = lane & 7;
    const int arow = ((T & 1) << 3) + la;    // A-frag row component
    const int akb  = (T >> 1) << 3;          // A-frag k component
    const int brow = ((T >> 1) << 3) + la;   // B-frag n component
    const int bkb  = (T & 1) << 3;           // B-frag k component
    const int vrow = ((T & 1) << 3) + la;    // V (trans) k component
    const int vcol = (T >> 1) << 3;          // V (trans) n component

    const size_t bh_off = (size_t)bh * SEQ * HDIM;

    // ---- stage Q (hi at 0, lo at +128*APITCH) ----
    {
        const size_t q0 = bh_off + (size_t)qb * 128 * HDIM;
#pragma unroll
        for (int i = 0; i < 8; i++) {
            int c = i * 256 + tid;       // 0..2047
            int op = c >> 10;            // 0=h 1=l
            int rem = c & 1023;
            int row = rem >> 3;          // 0..127
            int u = rem & 7;             // 16B unit
            const __nv_bfloat16* g = (op ? g_Ql : g_Qh) + q0 + (size_t)row * HDIM + u * 8;
            cp_async16(sbase + (uint32_t)(op * 128 * APITCH + row * APITCH + u * 16), g);
        }
        cp_commit();
        cp_wait0();
        __syncthreads();
    }

    // Q frags to regs
    uint32_t qh[4][4], ql[4][4];
#pragma unroll
    for (int kk = 0; kk < 4; kk++) {
        uint32_t off = (uint32_t)((w * 16 + arow) * APITCH + (kk * 16 + akb) * 2);
        ldsm_x4(qh[kk], sbase + off);
        ldsm_x4(ql[kk], sbase + (uint32_t)(128 * APITCH) + off);
    }
    __syncthreads();   // done reading Q staging before KV overwrites

    // ---- KV prefetch ----
    auto load_kv = [&](int it) {
        const size_t kv0 = bh_off + (size_t)it * 64 * HDIM;
        const uint32_t sb = sbase + (uint32_t)((it & 1) * 3 * ATILE_B);
#pragma unroll
        for (int i = 0; i < 6; i++) {
            int c = i * 256 + tid;       // 0..1535
            int op = c >> 9;             // 0=Kh 1=Kl 2=V
            int rem = c & 511;
            int row = rem >> 3;          // 0..63
            int u = rem & 7;
            const char* g;
            if (op == 0)      g = (const char*)(g_Kh + kv0 + (size_t)row * HDIM + u * 8);
            else if (op == 1) g = (const char*)(g_Kl + kv0 + (size_t)row * HDIM + u * 8);
            else              g = (const char*)(g_Vh + kv0 + (size_t)row * HDIM + u * 8);
            cp_async16(sb + (uint32_t)(op * ATILE_B + row * APITCH + u * 16), g);
        }
        cp_commit();
    };

    load_kv(0);
    load_kv(1);

    float o[8][4];
#pragma unroll
    for (int n = 0; n < 8; n++)
#pragma unroll
        for (int k = 0; k < 4; k++) o[n][k] = 0.f;
    float mA = -1e30f, mB = -1e30f, lA = 0.f, lB = 0.f;

    const int NIT = SEQ / 64;   // 32
    for (int it = 0; it < NIT; it++) {
        if (it + 1 < NIT) cp_wait1(); else cp_wait0();
        __syncthreads();

        const uint32_t sb  = sbase + (uint32_t)((it & 1) * 3 * ATILE_B);
        const uint32_t sKh = sb;
        const uint32_t sKl = sb + ATILE_B;
        const uint32_t sV  = sb + 2 * ATILE_B;

        // ---- S = Q K^T (3-term split) ----
        float s[8][4];
#pragma unroll
        for (int n = 0; n < 8; n++)
#pragma unroll
            for (int k = 0; k < 4; k++) s[n][k] = 0.f;

#pragma unroll
        for (int kk = 0; kk < 4; kk++) {
#pragma unroll
            for (int j = 0; j < 4; j++) {
                uint32_t kh[4], kl[4];
                uint32_t off = (uint32_t)((j * 16 + brow) * APITCH + (kk * 16 + bkb) * 2);
                ldsm_x4(kh, sKh + off);
                ldsm_x4(kl, sKl + off);
                mma_bf16(s[2 * j + 0], qh[kk], kh + 0);
                mma_bf16(s[2 * j + 0], qh[kk], kl + 0);
                mma_bf16(s[2 * j + 0], ql[kk], kh + 0);
                mma_bf16(s[2 * j + 1], qh[kk], kh + 2);
                mma_bf16(s[2 * j + 1], qh[kk], kl + 2);
                mma_bf16(s[2 * j + 1], ql[kk], kh + 2);
            }
        }

        // ---- online softmax (rows rA = lane>>2, rB = rA+8) ----
        float mxA = -1e30f, mxB = -1e30f;
#pragma unroll
        for (int n = 0; n < 8; n++) {
            mxA = fmaxf(mxA, fmaxf(s[n][0], s[n][1]));
            mxB = fmaxf(mxB, fmaxf(s[n][2], s[n][3]));
        }
        mxA = fmaxf(mxA, __shfl_xor_sync(0xffffffffu, mxA, 1));
        mxA = fmaxf(mxA, __shfl_xor_sync(0xffffffffu, mxA, 2));
        mxB = fmaxf(mxB, __shfl_xor_sync(0xffffffffu, mxB, 1));
        mxB = fmaxf(mxB, __shfl_xor_sync(0xffffffffu, mxB, 2));

        float mAn = fmaxf(mA, mxA);
        float mBn = fmaxf(mB, mxB);
        float nmA = mAn * LOG2E_F;
        float nmB = mBn * LOG2E_F;
        float alphaA = ex2f(mA * LOG2E_F - nmA);
        float alphaB = ex2f(mB * LOG2E_F - nmB);
        mA = mAn; mB = mBn;

        float sumA = 0.f, sumB = 0.f;
        uint32_t pa[8], pb[8];
#pragma unroll
        for (int n = 0; n < 8; n++) {
            float p0 = ex2f(fmaf(s[n][0], LOG2E_F, -nmA));
            float p1 = ex2f(fmaf(s[n][1], LOG2E_F, -nmA));
            float p2 = ex2f(fmaf(s[n][2], LOG2E_F, -nmB));
            float p3 = ex2f(fmaf(s[n][3], LOG2E_F, -nmB));
            sumA += p0 + p1;
            sumB += p2 + p3;
            pa[n] = pack_f16x2(p0, p1);
            pb[n] = pack_f16x2(p2, p3);
        }
        sumA += __shfl_xor_sync(0xffffffffu, sumA, 1);
        sumA += __shfl_xor_sync(0xffffffffu, sumA, 2);
        sumB += __shfl_xor_sync(0xffffffffu, sumB, 1);
        sumB += __shfl_xor_sync(0xffffffffu, sumB, 2);
        lA = lA * alphaA + sumA;
        lB = lB * alphaB + sumB;

#pragma unroll
        for (int n = 0; n < 8; n++) {
            o[n][0] *= alphaA; o[n][1] *= alphaA;
            o[n][2] *= alphaB; o[n][3] *= alphaB;
        }

        // ---- O += P V  (fp16) ----
#pragma unroll
        for (int kk = 0; kk < 4; kk++) {
            uint32_t a[4] = { pa[2 * kk], pb[2 * kk], pa[2 * kk + 1], pb[2 * kk + 1] };
#pragma unroll
            for (int j = 0; j < 4; j++) {
                uint32_t vb[4];
                uint32_t off = (uint32_t)((kk * 16 + vrow) * APITCH + (j * 16 + vcol) * 2);
                ldsm_x4_t(vb, sV + off);
                mma_f16(o[2 * j + 0], a, vb + 0);
                mma_f16(o[2 * j + 1], a, vb + 2);
            }
        }

        __syncthreads();   // all reads of this stage done before reload
        if (it + 2 < NIT) load_kv(it + 2);
    }

    // ---- epilogue: normalize + bf16 split -> g_oh / g_ol ----
    const int b = bh / HEADS;
    const int h = bh - b * HEADS;
    const float invA = 1.0f / lA;
    const float invB = 1.0f / lB;
    const int tA = qb * 128 + w * 16 + (lane >> 2);
    const int tB = tA + 8;
#pragma unroll
    for (int n = 0; n < 8; n++) {
        int c = h * 64 + n * 8 + ((lane & 3) << 1);
        size_t offA = ((size_t)b * SEQ + tA) * DIM + c;
        size_t offB = ((size_t)b * SEQ + tB) * DIM + c;
        float vx = o[n][0] * invA, vy = o[n][1] * invA;
        __nv_bfloat16 hx = __float2bfloat16_rn(vx);
        __nv_bfloat16 hy = __float2bfloat16_rn(vy);
        __nv_bfloat162 hv; hv.x = hx; hv.y = hy;
        __nv_bfloat162 lv;
        lv.x = __float2bfloat16_rn(vx - __bfloat162float(hx));
        lv.y = __float2bfloat16_rn(vy - __bfloat162float(hy));
        *(__nv_bfloat162*)&g_oh[offA] = hv;
        *(__nv_bfloat162*)&g_ol[offA] = lv;

        vx = o[n][2] * invB; vy = o[n][3] * invB;
        hx = __float2bfloat16_rn(vx); hy = __float2bfloat16_rn(vy);
        hv.x = hx; hv.y = hy;
        lv.x = __float2bfloat16_rn(vx - __bfloat162float(hx));
        lv.y = __float2bfloat16_rn(vy - __bfloat162float(hy));
        *(__nv_bfloat162*)&g_oh[offB] = hv;
        *(__nv_bfloat162*)&g_ol[offB] = lv;
    }
}

// ---------------------------------------------------------------------------
extern "C" void kernel_launch(void* const* d_in, const int* in_sizes, int n_in,
                              void* d_out, int out_size)
{
    (void)in_sizes; (void)n_in; (void)out_size;
    const float* x      = (const float*)d_in[0];
    const float* qkv_w  = (const float*)d_in[1];
    const float* q_bias = (const float*)d_in[2];
    const float* v_bias = (const float*)d_in[3];
    const float* proj_w = (const float*)d_in[4];
    const float* proj_b = (const float*)d_in[5];
    float* out = (float*)d_out;

    cudaFuncSetAttribute(gemm_mma<0>, cudaFuncAttributeMaxDynamicSharedMemorySize, GEMM_SMEM);
    cudaFuncSetAttribute(gemm_mma<1>, cudaFuncAttributeMaxDynamicSharedMemorySize, GEMM_SMEM);
    cudaFuncSetAttribute(attn_mma,    cudaFuncAttributeMaxDynamicSharedMemorySize, ATTN_SMEM);

    // 0) split fp32 -> bf16 hi/lo
    convert_split_exact<0><<<(BATCH * SEQ * DIM / 2 + 255) / 256, 256>>>(x, BATCH * SEQ * DIM / 2);
    convert_split_exact<1><<<(3 * DIM * DIM / 2 + 255) / 256, 256>>>(qkv_w, 3 * DIM * DIM / 2);
    convert_split_exact<2><<<(DIM * DIM / 2 + 255) / 256, 256>>>(proj_w, DIM * DIM / 2);

    // 1) QKV GEMM (HMMA) -> split Q/K bf16 + V fp16
    gemm_mma<0><<<dim3(3 * DIM / 128, BATCH * SEQ / 128), 256, GEMM_SMEM>>>(
        q_bias, v_bias, nullptr);

    // 2) Flash attention (HMMA) -> split O bf16
    attn_mma<<<dim3(SEQ / 128, BATCH * HEADS), 256, ATTN_SMEM>>>();

    // 3) Projection GEMM (HMMA) + bias
    gemm_mma<1><<<dim3(DIM / 128, BATCH * SEQ / 128), 256, GEMM_SMEM>>>(
        proj_b, nullptr, out);
}

// round 6
// speedup vs baseline: 4.0360x; 1.1048x over previous
#include <cuda_runtime.h>
#include <cuda_bf16.h>
#include <cuda_fp16.h>
#include <cstdint>

#define BATCH 4
#define SEQ   2048
#define DIM   768
#define HEADS 12
#define HDIM  64
#define SCALE_F 0.125f   // 64^-0.5
#define LOG2E_F 1.4426950408889634f

// ---------------------------------------------------------------------------
// Scratch (allocation-free rule: __device__ globals)
// ---------------------------------------------------------------------------
static __device__ __nv_bfloat16 g_Qh[(size_t)BATCH * HEADS * SEQ * HDIM];
static __device__ __nv_bfloat16 g_Ql[(size_t)BATCH * HEADS * SEQ * HDIM];
static __device__ __nv_bfloat16 g_Kh[(size_t)BATCH * HEADS * SEQ * HDIM];
static __device__ __nv_bfloat16 g_Kl[(size_t)BATCH * HEADS * SEQ * HDIM];
static __device__ __half        g_Vh[(size_t)BATCH * HEADS * SEQ * HDIM];

static __device__ __nv_bfloat16 g_xh[(size_t)BATCH * SEQ * DIM];
static __device__ __nv_bfloat16 g_xl[(size_t)BATCH * SEQ * DIM];
static __device__ __nv_bfloat16 g_wqh[(size_t)3 * DIM * DIM];
static __device__ __nv_bfloat16 g_wql[(size_t)3 * DIM * DIM];
static __device__ __nv_bfloat16 g_oh[(size_t)BATCH * SEQ * DIM];
static __device__ __nv_bfloat16 g_ol[(size_t)BATCH * SEQ * DIM];
static __device__ __nv_bfloat16 g_wph[(size_t)DIM * DIM];
static __device__ __nv_bfloat16 g_wpl[(size_t)DIM * DIM];

// ---------------------------------------------------------------------------
// helpers
// ---------------------------------------------------------------------------
__device__ __forceinline__ uint32_t smem_to_u32(const void* p) {
    uint32_t a;
    asm("{ .reg .u64 t; cvta.to.shared.u64 t, %1; cvt.u32.u64 %0, t; }"
        : "=r"(a) : "l"(p));
    return a;
}
__device__ __forceinline__ void cp_async16(uint32_t saddr, const void* gaddr) {
    asm volatile("cp.async.cg.shared.global [%0], [%1], 16;"
                 :: "r"(saddr), "l"(gaddr));
}
__device__ __forceinline__ void cp_commit() {
    asm volatile("cp.async.commit_group;");
}
__device__ __forceinline__ void cp_wait0() {
    asm volatile("cp.async.wait_group 0;" ::: "memory");
}
__device__ __forceinline__ void cp_wait1() {
    asm volatile("cp.async.wait_group 1;" ::: "memory");
}
__device__ __forceinline__ void cp_wait2() {
    asm volatile("cp.async.wait_group 2;" ::: "memory");
}
__device__ __forceinline__ void cp_wait3() {
    asm volatile("cp.async.wait_group 3;" ::: "memory");
}
__device__ __forceinline__ void ldsm_x4(uint32_t* r, uint32_t addr) {
    asm volatile("ldmatrix.sync.aligned.m8n8.x4.shared.b16 {%0,%1,%2,%3}, [%4];"
                 : "=r"(r[0]), "=r"(r[1]), "=r"(r[2]), "=r"(r[3]) : "r"(addr));
}
__device__ __forceinline__ void ldsm_x4_t(uint32_t* r, uint32_t addr) {
    asm volatile("ldmatrix.sync.aligned.m8n8.x4.trans.shared.b16 {%0,%1,%2,%3}, [%4];"
                 : "=r"(r[0]), "=r"(r[1]), "=r"(r[2]), "=r"(r[3]) : "r"(addr));
}
__device__ __forceinline__ void mma_bf16(float* d, const uint32_t* a,
                                         const uint32_t* b) {
    asm volatile(
        "mma.sync.aligned.m16n8k16.row.col.f32.bf16.bf16.f32 "
        "{%0,%1,%2,%3}, {%4,%5,%6,%7}, {%8,%9}, {%0,%1,%2,%3};"
        : "+f"(d[0]), "+f"(d[1]), "+f"(d[2]), "+f"(d[3])
        : "r"(a[0]), "r"(a[1]), "r"(a[2]), "r"(a[3]), "r"(b[0]), "r"(b[1]));
}
__device__ __forceinline__ void mma_f16(float* d, const uint32_t* a,
                                        const uint32_t* b) {
    asm volatile(
        "mma.sync.aligned.m16n8k16.row.col.f32.f16.f16.f32 "
        "{%0,%1,%2,%3}, {%4,%5,%6,%7}, {%8,%9}, {%0,%1,%2,%3};"
        : "+f"(d[0]), "+f"(d[1]), "+f"(d[2]), "+f"(d[3])
        : "r"(a[0]), "r"(a[1]), "r"(a[2]), "r"(a[3]), "r"(b[0]), "r"(b[1]));
}
__device__ __forceinline__ float ex2f(float x) {
    float r;
    asm("ex2.approx.f32 %0, %1;" : "=f"(r) : "f"(x));
    return r;
}
__device__ __forceinline__ uint32_t pack_f16x2(float lo, float hi) {
    uint32_t r;
    asm("cvt.rn.f16x2.f32 %0, %1, %2;" : "=r"(r) : "f"(hi), "f"(lo));
    return r;
}
// 64B-pitch rows (GEMM: BK=32 bf16 = 64B), XOR swizzle over 4x16B units
__device__ __forceinline__ uint32_t swz64(int row, int u) {
    return (uint32_t)(row * 64 + ((u ^ ((row >> 1) & 3)) << 4));
}
// 128B-pitch rows (attention: 64 bf16/f16x64... = 128B), XOR over 8x16B units
__device__ __forceinline__ uint32_t swz128(int row, int u) {
    return (uint32_t)(row * 128 + ((u ^ (row & 7)) << 4));
}

// ---------------------------------------------------------------------------
// fp32 -> bf16 hi/lo split  (0=x, 1=qkv_w, 2=proj_w)
// ---------------------------------------------------------------------------
template <int WHICH>
__global__ void convert_split_exact(const float* __restrict__ in, int n2)
{
    __nv_bfloat162* hi;
    __nv_bfloat162* lo;
    if (WHICH == 0) { hi = (__nv_bfloat162*)g_xh;  lo = (__nv_bfloat162*)g_xl; }
    if (WHICH == 1) { hi = (__nv_bfloat162*)g_wqh; lo = (__nv_bfloat162*)g_wql; }
    if (WHICH == 2) { hi = (__nv_bfloat162*)g_wph; lo = (__nv_bfloat162*)g_wpl; }

    int i = blockIdx.x * blockDim.x + threadIdx.x;
    if (i < n2) {
        float2 v = ((const float2*)in)[i];
        __nv_bfloat16 hx = __float2bfloat16_rn(v.x);
        __nv_bfloat16 hy = __float2bfloat16_rn(v.y);
        __nv_bfloat162 h; h.x = hx; h.y = hy;
        hi[i] = h;
        __nv_bfloat162 l;
        l.x = __float2bfloat16_rn(v.x - __bfloat162float(hx));
        l.y = __float2bfloat16_rn(v.y - __bfloat162float(hy));
        lo[i] = l;
    }
}

// ---------------------------------------------------------------------------
// HMMA GEMM, 3-stage cp.async pipeline, swizzled 64B-pitch smem. (round-5, OK)
// CTA 128x128, BK=32, 8 warps (2M x 4N), warp tile 64x32. 2 CTAs/SM.
// ---------------------------------------------------------------------------
#define OP_B    (128 * 64)            // 8192 per operand tile
#define STAGE_B (4 * OP_B)            // 32768 per stage
static constexpr int GEMM_SMEM = 3 * STAGE_B;  // 98304

template <int MODE>
__global__ void __launch_bounds__(256, 2) gemm_mma(
    const float* __restrict__ bias1, const float* __restrict__ bias2,
    float* __restrict__ out)
{
    constexpr int K = DIM;
    constexpr int NST = K / 32;       // 24

    extern __shared__ char smem[];
    const uint32_t sbase = smem_to_u32(smem);

    const __nv_bfloat16* Ah = (MODE == 0) ? g_xh : g_oh;
    const __nv_bfloat16* Al = (MODE == 0) ? g_xl : g_ol;
    const __nv_bfloat16* Wh = (MODE == 0) ? g_wqh : g_wph;
    const __nv_bfloat16* Wl = (MODE == 0) ? g_wql : g_wpl;
    const __nv_bfloat16* gsrc[4] = { Ah, Al, Wh, Wl };

    const int tid  = threadIdx.x;
    const int lane = tid & 31;
    const int wid  = tid >> 5;
    const int mw   = wid >> 2;
    const int nw   = wid & 3;
    const int m0   = blockIdx.y * 128;
    const int n0   = blockIdx.x * 128;

    const int T   = lane >> 3;
    const int la  = lane & 7;
    const int arow = ((T & 1) << 3) + la;
    const int au   = T >> 1;
    const int brow = ((T >> 1) << 3) + la;
    const int bu   = T & 1;
    const int aswz = (arow >> 1) & 3;
    const int bswz = (brow >> 1) & 3;

    float acc[4][4][4];
#pragma unroll
    for (int i = 0; i < 4; i++)
#pragma unroll
        for (int j = 0; j < 4; j++)
#pragma unroll
            for (int k = 0; k < 4; k++) acc[i][j][k] = 0.f;

    auto load_stage = [&](int kb) {
        const int kq = kb * 32;
        const uint32_t sb = sbase + (uint32_t)((kb % 3) * STAGE_B);
#pragma unroll
        for (int i = 0; i < 8; i++) {
            int c   = i * 256 + tid;      // 0..2047
            int op  = c >> 9;
            int rem = c & 511;
            int row = rem >> 2;
            int u   = rem & 3;
            int grow = (op < 2) ? (m0 + row) : (n0 + row);
            const __nv_bfloat16* g = gsrc[op] + (size_t)grow * K + kq + u * 8;
            cp_async16(sb + (uint32_t)(op * OP_B) + swz64(row, u), g);
        }
        cp_commit();
    };

    load_stage(0);
    load_stage(1);
    load_stage(2);

    for (int kb = 0; kb < NST; kb++) {
        if (kb + 2 < NST) cp_wait2();
        else if (kb + 1 < NST) cp_wait1();
        else cp_wait0();
        __syncthreads();

        const uint32_t sb  = sbase + (uint32_t)((kb % 3) * STAGE_B);
        const uint32_t bAh = sb;
        const uint32_t bAl = sb + OP_B;
        const uint32_t bWh = sb + 2 * OP_B;
        const uint32_t bWl = sb + 3 * OP_B;

#pragma unroll
        for (int kk = 0; kk < 2; kk++) {
            uint32_t ah[4][4], al[4][4], wh[2][4], wl[2][4];
            const int uA = 2 * kk + au;
            const int uB = 2 * kk + bu;
#pragma unroll
            for (int ma = 0; ma < 4; ma++) {
                int row = mw * 64 + ma * 16 + arow;
                uint32_t off = (uint32_t)(row * 64 + ((uA ^ aswz) << 4));
                ldsm_x4(ah[ma], bAh + off);
                ldsm_x4(al[ma], bAl + off);
            }
#pragma unroll
            for (int nb = 0; nb < 2; nb++) {
                int row = nw * 32 + nb * 16 + brow;
                uint32_t off = (uint32_t)(row * 64 + ((uB ^ bswz) << 4));
                ldsm_x4(wh[nb], bWh + off);
                ldsm_x4(wl[nb], bWl + off);
            }
#pragma unroll
            for (int ma = 0; ma < 4; ma++)
#pragma unroll
                for (int na = 0; na < 4; na++) {
                    const uint32_t* bh = &wh[na >> 1][(na & 1) * 2];
                    const uint32_t* bl = &wl[na >> 1][(na & 1) * 2];
                    mma_bf16(acc[ma][na], ah[ma], bh);
                    mma_bf16(acc[ma][na], ah[ma], bl);
                    mma_bf16(acc[ma][na], al[ma], bh);
                }
        }
        __syncthreads();
        if (kb + 3 < NST) load_stage(kb + 3);
    }

    const int qrow = lane >> 2;
    const int qcol = (lane & 3) << 1;

    if (MODE == 0) {
        const int sec = blockIdx.x / 6;            // 0=q 1=k 2=v
        const int nl0 = (blockIdx.x % 6) * 128;
#pragma unroll
        for (int na = 0; na < 4; na++) {
            const int c = nl0 + nw * 32 + na * 8 + qcol;   // 0..767
            const int h = c >> 6, d = c & 63;
            float bx = 0.f, by = 0.f;
            if (sec == 0) { bx = bias1[c]; by = bias1[c + 1]; }
            if (sec == 2) { bx = bias2[c]; by = bias2[c + 1]; }
#pragma unroll
            for (int ma = 0; ma < 4; ma++) {
                const int mr = m0 + mw * 64 + ma * 16 + qrow;
#pragma unroll
                for (int half = 0; half < 2; half++) {
                    int m = mr + half * 8;
                    int b = m >> 11, t = m & 2047;
                    float vx = acc[ma][na][half * 2 + 0] + bx;
                    float vy = acc[ma][na][half * 2 + 1] + by;
                    size_t off = ((((size_t)b * HEADS + h) * SEQ + t) << 6) + d;
                    if (sec == 2) {
                        *(__half2*)&g_Vh[off] = __floats2half2_rn(vx, vy);
                    } else {
                        if (sec == 0) { vx *= SCALE_F; vy *= SCALE_F; }
                        __nv_bfloat16 hx = __float2bfloat16_rn(vx);
                        __nv_bfloat16 hy = __float2bfloat16_rn(vy);
                        __nv_bfloat162 hv; hv.x = hx; hv.y = hy;
                        __nv_bfloat162 lv;
                        lv.x = __float2bfloat16_rn(vx - __bfloat162float(hx));
                        lv.y = __float2bfloat16_rn(vy - __bfloat162float(hy));
                        if (sec == 0) {
                            *(__nv_bfloat162*)&g_Qh[off] = hv;
                            *(__nv_bfloat162*)&g_Ql[off] = lv;
                        } else {
                            *(__nv_bfloat162*)&g_Kh[off] = hv;
                            *(__nv_bfloat162*)&g_Kl[off] = lv;
                        }
                    }
                }
            }
        }
    } else {
#pragma unroll
        for (int na = 0; na < 4; na++) {
            const int n = n0 + nw * 32 + na * 8 + qcol;
            const float bx = bias1[n], by = bias1[n + 1];
#pragma unroll
            for (int ma = 0; ma < 4; ma++) {
                const int mr = m0 + mw * 64 + ma * 16 + qrow;
#pragma unroll
                for (int half = 0; half < 2; half++) {
                    int m = mr + half * 8;
                    float2 v;
                    v.x = acc[ma][na][half * 2 + 0] + bx;
                    v.y = acc[ma][na][half * 2 + 1] + by;
                    *(float2*)&out[(size_t)m * DIM + n] = v;
                }
            }
        }
    }
}

// ---------------------------------------------------------------------------
// HMMA flash attention, 3-stage KV prefetch, 128B-pitch XOR-swizzled smem.
// Br=128, Bc=64, 8 warps. QK bf16 3-term; softmax in regs; PV fp16.
// smem: Qh[16K] Ql[16K] at 0; KV stages (Kh,Kl,V) 3 x 24K from 32768.
// ---------------------------------------------------------------------------
#define AQ_B    (128 * 128)             // 16384 per Q operand
#define AKV_OP  (64 * 128)              // 8192 per KV operand
#define AKV_ST  (3 * AKV_OP)            // 24576 per stage
static constexpr int ATTN_SMEM = 2 * AQ_B + 3 * AKV_ST;  // 106496

__global__ void __launch_bounds__(256) attn_mma()
{
    extern __shared__ char smem[];
    const uint32_t sbase = smem_to_u32(smem);
    const uint32_t kvbase = sbase + 2 * AQ_B;

    const int tid  = threadIdx.x;
    const int lane = tid & 31;
    const int w    = tid >> 5;
    const int qb   = blockIdx.x;      // 0..15
    const int bh   = blockIdx.y;      // 0..47

    const int T  = lane >> 3;
    const int la = lane & 7;
    const int arow = ((T & 1) << 3) + la;    // A-frag row
    const int au   = T >> 1;                 // A-frag k-unit bit
    const int brow = ((T >> 1) << 3) + la;   // B-frag row
    const int bu   = T & 1;                  // B-frag k-unit bit
    const int vrow = ((T & 1) << 3) + la;    // V trans k row
    const int vu   = T >> 1;                 // V trans n-unit bit

    const size_t bh_off = (size_t)bh * SEQ * HDIM;

    // ---- stage Q (hi at 0, lo at +AQ_B): 2 ops x 128 rows x 8 units ----
    {
        const size_t q0 = bh_off + (size_t)qb * 128 * HDIM;
#pragma unroll
        for (int i = 0; i < 8; i++) {
            int c = i * 256 + tid;       // 0..2047
            int op = c >> 10;            // 0=h 1=l
            int rem = c & 1023;
            int row = rem >> 3;          // 0..127
            int u = rem & 7;
            const __nv_bfloat16* g = (op ? g_Ql : g_Qh) + q0 + (size_t)row * HDIM + u * 8;
            cp_async16(sbase + (uint32_t)(op * AQ_B) + swz128(row, u), g);
        }
        cp_commit();
    }

    // ---- KV prefetch: 3 ops x 64 rows x 8 units = 1536 chunks ----
    auto load_kv = [&](int it) {
        const size_t kv0 = bh_off + (size_t)it * 64 * HDIM;
        const uint32_t sb = kvbase + (uint32_t)((it % 3) * AKV_ST);
#pragma unroll
        for (int i = 0; i < 6; i++) {
            int c = i * 256 + tid;       // 0..1535
            int op = c >> 9;             // 0=Kh 1=Kl 2=V
            int rem = c & 511;
            int row = rem >> 3;          // 0..63
            int u = rem & 7;
            const char* g;
            if (op == 0)      g = (const char*)(g_Kh + kv0 + (size_t)row * HDIM + u * 8);
            else if (op == 1) g = (const char*)(g_Kl + kv0 + (size_t)row * HDIM + u * 8);
            else              g = (const char*)(g_Vh + kv0 + (size_t)row * HDIM + u * 8);
            cp_async16(sb + (uint32_t)(op * AKV_OP) + swz128(row, u), g);
        }
        cp_commit();
    };

    load_kv(0);
    load_kv(1);
    load_kv(2);

    // Q group done (3 KV groups still pending)
    cp_wait3();
    __syncthreads();

    uint32_t qh[4][4], ql[4][4];
#pragma unroll
    for (int kk = 0; kk < 4; kk++) {
        int row = w * 16 + arow;
        int u = 2 * kk + au;
        uint32_t off = swz128(row, u);
        ldsm_x4(qh[kk], sbase + off);
        ldsm_x4(ql[kk], sbase + (uint32_t)AQ_B + off);
    }

    float o[8][4];
#pragma unroll
    for (int n = 0; n < 8; n++)
#pragma unroll
        for (int k = 0; k < 4; k++) o[n][k] = 0.f;
    float mA = -1e30f, mB = -1e30f, lA = 0.f, lB = 0.f;

    const int NIT = SEQ / 64;   // 32
    for (int it = 0; it < NIT; it++) {
        if (it + 2 < NIT) cp_wait2();
        else if (it + 1 < NIT) cp_wait1();
        else cp_wait0();
        __syncthreads();

        const uint32_t sb  = kvbase + (uint32_t)((it % 3) * AKV_ST);
        const uint32_t sKh = sb;
        const uint32_t sKl = sb + AKV_OP;
        const uint32_t sV  = sb + 2 * AKV_OP;

        // ---- S = Q K^T (3-term split) ----
        float s[8][4];
#pragma unroll
        for (int n = 0; n < 8; n++)
#pragma unroll
            for (int k = 0; k < 4; k++) s[n][k] = 0.f;

#pragma unroll
        for (int kk = 0; kk < 4; kk++) {
#pragma unroll
            for (int j = 0; j < 4; j++) {
                uint32_t kh[4], kl[4];
                int row = j * 16 + brow;
                int u = 2 * kk + bu;
                uint32_t off = swz128(row, u);
                ldsm_x4(kh, sKh + off);
                ldsm_x4(kl, sKl + off);
                mma_bf16(s[2 * j + 0], qh[kk], kh + 0);
                mma_bf16(s[2 * j + 0], qh[kk], kl + 0);
                mma_bf16(s[2 * j + 0], ql[kk], kh + 0);
                mma_bf16(s[2 * j + 1], qh[kk], kh + 2);
                mma_bf16(s[2 * j + 1], qh[kk], kl + 2);
                mma_bf16(s[2 * j + 1], ql[kk], kh + 2);
            }
        }

        // ---- online softmax ----
        float mxA = -1e30f, mxB = -1e30f;
#pragma unroll
        for (int n = 0; n < 8; n++) {
            mxA = fmaxf(mxA, fmaxf(s[n][0], s[n][1]));
            mxB = fmaxf(mxB, fmaxf(s[n][2], s[n][3]));
        }
        mxA = fmaxf(mxA, __shfl_xor_sync(0xffffffffu, mxA, 1));
        mxA = fmaxf(mxA, __shfl_xor_sync(0xffffffffu, mxA, 2));
        mxB = fmaxf(mxB, __shfl_xor_sync(0xffffffffu, mxB, 1));
        mxB = fmaxf(mxB, __shfl_xor_sync(0xffffffffu, mxB, 2));

        float mAn = fmaxf(mA, mxA);
        float mBn = fmaxf(mB, mxB);
        float nmA = mAn * LOG2E_F;
        float nmB = mBn * LOG2E_F;
        float alphaA = ex2f(mA * LOG2E_F - nmA);
        float alphaB = ex2f(mB * LOG2E_F - nmB);
        mA = mAn; mB = mBn;

        float sumA = 0.f, sumB = 0.f;
        uint32_t pa[8], pb[8];
#pragma unroll
        for (int n = 0; n < 8; n++) {
            float p0 = ex2f(fmaf(s[n][0], LOG2E_F, -nmA));
            float p1 = ex2f(fmaf(s[n][1], LOG2E_F, -nmA));
            float p2 = ex2f(fmaf(s[n][2], LOG2E_F, -nmB));
            float p3 = ex2f(fmaf(s[n][3], LOG2E_F, -nmB));
            sumA += p0 + p1;
            sumB += p2 + p3;
            pa[n] = pack_f16x2(p0, p1);
            pb[n] = pack_f16x2(p2, p3);
        }
        sumA += __shfl_xor_sync(0xffffffffu, sumA, 1);
        sumA += __shfl_xor_sync(0xffffffffu, sumA, 2);
        sumB += __shfl_xor_sync(0xffffffffu, sumB, 1);
        sumB += __shfl_xor_sync(0xffffffffu, sumB, 2);
        lA = lA * alphaA + sumA;
        lB = lB * alphaB + sumB;

#pragma unroll
        for (int n = 0; n < 8; n++) {
            o[n][0] *= alphaA; o[n][1] *= alphaA;
            o[n][2] *= alphaB; o[n][3] *= alphaB;
        }

        // ---- O += P V (fp16, trans B-frags) ----
#pragma unroll
        for (int kk = 0; kk < 4; kk++) {
            uint32_t a[4] = { pa[2 * kk], pb[2 * kk], pa[2 * kk + 1], pb[2 * kk + 1] };
#pragma unroll
            for (int j = 0; j < 4; j++) {
                uint32_t vb[4];
                int row = kk * 16 + vrow;     // k position
                int u = 2 * j + vu;           // n-unit
                uint32_t off = swz128(row, u);
                ldsm_x4_t(vb, sV + off);
                mma_f16(o[2 * j + 0], a, vb + 0);
                mma_f16(o[2 * j + 1], a, vb + 2);
            }
        }

        __syncthreads();
        if (it + 3 < NIT) load_kv(it + 3);
    }

    // ---- epilogue: normalize + bf16 split -> g_oh / g_ol ----
    const int b = bh / HEADS;
    const int h = bh - b * HEADS;
    const float invA = 1.0f / lA;
    const float invB = 1.0f / lB;
    const int tA = qb * 128 + w * 16 + (lane >> 2);
    const int tB = tA + 8;
#pragma unroll
    for (int n = 0; n < 8; n++) {
        int c = h * 64 + n * 8 + ((lane & 3) << 1);
        size_t offA = ((size_t)b * SEQ + tA) * DIM + c;
        size_t offB = ((size_t)b * SEQ + tB) * DIM + c;
        float vx = o[n][0] * invA, vy = o[n][1] * invA;
        __nv_bfloat16 hx = __float2bfloat16_rn(vx);
        __nv_bfloat16 hy = __float2bfloat16_rn(vy);
        __nv_bfloat162 hv; hv.x = hx; hv.y = hy;
        __nv_bfloat162 lv;
        lv.x = __float2bfloat16_rn(vx - __bfloat162float(hx));
        lv.y = __float2bfloat16_rn(vy - __bfloat162float(hy));
        *(__nv_bfloat162*)&g_oh[offA] = hv;
        *(__nv_bfloat162*)&g_ol[offA] = lv;

        vx = o[n][2] * invB; vy = o[n][3] * invB;
        hx = __float2bfloat16_rn(vx); hy = __float2bfloat16_rn(vy);
        hv.x = hx; hv.y = hy;
        lv.x = __float2bfloat16_rn(vx - __bfloat162float(hx));
        lv.y = __float2bfloat16_rn(vy - __bfloat162float(hy));
        *(__nv_bfloat162*)&g_oh[offB] = hv;
        *(__nv_bfloat162*)&g_ol[offB] = lv;
    }
}

// ---------------------------------------------------------------------------
extern "C" void kernel_launch(void* const* d_in, const int* in_sizes, int n_in,
                              void* d_out, int out_size)
{
    (void)in_sizes; (void)n_in; (void)out_size;
    const float* x      = (const float*)d_in[0];
    const float* qkv_w  = (const float*)d_in[1];
    const float* q_bias = (const float*)d_in[2];
    const float* v_bias = (const float*)d_in[3];
    const float* proj_w = (const float*)d_in[4];
    const float* proj_b = (const float*)d_in[5];
    float* out = (float*)d_out;

    cudaFuncSetAttribute(gemm_mma<0>, cudaFuncAttributeMaxDynamicSharedMemorySize, GEMM_SMEM);
    cudaFuncSetAttribute(gemm_mma<1>, cudaFuncAttributeMaxDynamicSharedMemorySize, GEMM_SMEM);
    cudaFuncSetAttribute(attn_mma,    cudaFuncAttributeMaxDynamicSharedMemorySize, ATTN_SMEM);

    // 0) split fp32 -> bf16 hi/lo
    convert_split_exact<0><<<(BATCH * SEQ * DIM / 2 + 255) / 256, 256>>>(x, BATCH * SEQ * DIM / 2);
    convert_split_exact<1><<<(3 * DIM * DIM / 2 + 255) / 256, 256>>>(qkv_w, 3 * DIM * DIM / 2);
    convert_split_exact<2><<<(DIM * DIM / 2 + 255) / 256, 256>>>(proj_w, DIM * DIM / 2);

    // 1) QKV GEMM (HMMA) -> split Q/K bf16 + V fp16
    gemm_mma<0><<<dim3(3 * DIM / 128, BATCH * SEQ / 128), 256, GEMM_SMEM>>>(
        q_bias, v_bias, nullptr);

    // 2) Flash attention (HMMA) -> split O bf16
    attn_mma<<<dim3(SEQ / 128, BATCH * HEADS), 256, ATTN_SMEM>>>();

    // 3) Projection GEMM (HMMA) + bias
    gemm_mma<1><<<dim3(DIM / 128, BATCH * SEQ / 128), 256, GEMM_SMEM>>>(
        proj_b, nullptr, out);
}

// round 7
// speedup vs baseline: 5.1417x; 1.2740x over previous
#include <cuda_runtime.h>
#include <cuda_bf16.h>
#include <cuda_fp16.h>
#include <cstdint>

#define BATCH 4
#define SEQ   2048
#define DIM   768
#define HEADS 12
#define HDIM  64
#define SCALE_F 0.125f   // 64^-0.5
#define LOG2E_F 1.4426950408889634f

// ---------------------------------------------------------------------------
// Scratch (allocation-free rule: __device__ globals)
// ---------------------------------------------------------------------------
static __device__ __half g_Qf[(size_t)BATCH * HEADS * SEQ * HDIM];
static __device__ __half g_Kf[(size_t)BATCH * HEADS * SEQ * HDIM];
static __device__ __half g_Vh[(size_t)BATCH * HEADS * SEQ * HDIM];

static __device__ __nv_bfloat16 g_xh[(size_t)BATCH * SEQ * DIM];
static __device__ __nv_bfloat16 g_xl[(size_t)BATCH * SEQ * DIM];
static __device__ __nv_bfloat16 g_wqh[(size_t)3 * DIM * DIM];
static __device__ __nv_bfloat16 g_wql[(size_t)3 * DIM * DIM];
static __device__ __nv_bfloat16 g_oh[(size_t)BATCH * SEQ * DIM];
static __device__ __nv_bfloat16 g_ol[(size_t)BATCH * SEQ * DIM];
static __device__ __nv_bfloat16 g_wph[(size_t)DIM * DIM];
static __device__ __nv_bfloat16 g_wpl[(size_t)DIM * DIM];

// ---------------------------------------------------------------------------
// helpers
// ---------------------------------------------------------------------------
__device__ __forceinline__ uint32_t smem_to_u32(const void* p) {
    uint32_t a;
    asm("{ .reg .u64 t; cvta.to.shared.u64 t, %1; cvt.u32.u64 %0, t; }"
        : "=r"(a) : "l"(p));
    return a;
}
__device__ __forceinline__ void cp_async16(uint32_t saddr, const void* gaddr) {
    asm volatile("cp.async.cg.shared.global [%0], [%1], 16;"
                 :: "r"(saddr), "l"(gaddr));
}
__device__ __forceinline__ void cp_commit() {
    asm volatile("cp.async.commit_group;");
}
__device__ __forceinline__ void cp_wait0() {
    asm volatile("cp.async.wait_group 0;" ::: "memory");
}
__device__ __forceinline__ void cp_wait1() {
    asm volatile("cp.async.wait_group 1;" ::: "memory");
}
__device__ __forceinline__ void cp_wait2() {
    asm volatile("cp.async.wait_group 2;" ::: "memory");
}
__device__ __forceinline__ void cp_wait3() {
    asm volatile("cp.async.wait_group 3;" ::: "memory");
}
__device__ __forceinline__ void ldsm_x4(uint32_t* r, uint32_t addr) {
    asm volatile("ldmatrix.sync.aligned.m8n8.x4.shared.b16 {%0,%1,%2,%3}, [%4];"
                 : "=r"(r[0]), "=r"(r[1]), "=r"(r[2]), "=r"(r[3]) : "r"(addr));
}
__device__ __forceinline__ void ldsm_x4_t(uint32_t* r, uint32_t addr) {
    asm volatile("ldmatrix.sync.aligned.m8n8.x4.trans.shared.b16 {%0,%1,%2,%3}, [%4];"
                 : "=r"(r[0]), "=r"(r[1]), "=r"(r[2]), "=r"(r[3]) : "r"(addr));
}
__device__ __forceinline__ void mma_bf16(float* d, const uint32_t* a,
                                         const uint32_t* b) {
    asm volatile(
        "mma.sync.aligned.m16n8k16.row.col.f32.bf16.bf16.f32 "
        "{%0,%1,%2,%3}, {%4,%5,%6,%7}, {%8,%9}, {%0,%1,%2,%3};"
        : "+f"(d[0]), "+f"(d[1]), "+f"(d[2]), "+f"(d[3])
        : "r"(a[0]), "r"(a[1]), "r"(a[2]), "r"(a[3]), "r"(b[0]), "r"(b[1]));
}
__device__ __forceinline__ void mma_f16(float* d, const uint32_t* a,
                                        const uint32_t* b) {
    asm volatile(
        "mma.sync.aligned.m16n8k16.row.col.f32.f16.f16.f32 "
        "{%0,%1,%2,%3}, {%4,%5,%6,%7}, {%8,%9}, {%0,%1,%2,%3};"
        : "+f"(d[0]), "+f"(d[1]), "+f"(d[2]), "+f"(d[3])
        : "r"(a[0]), "r"(a[1]), "r"(a[2]), "r"(a[3]), "r"(b[0]), "r"(b[1]));
}
__device__ __forceinline__ float ex2f(float x) {
    float r;
    asm("ex2.approx.f32 %0, %1;" : "=f"(r) : "f"(x));
    return r;
}
__device__ __forceinline__ uint32_t pack_f16x2(float lo, float hi) {
    uint32_t r;
    asm("cvt.rn.f16x2.f32 %0, %1, %2;" : "=r"(r) : "f"(hi), "f"(lo));
    return r;
}
// 128B-pitch rows, XOR swizzle over 8x16B units (conflict-free ldmatrix)
__device__ __forceinline__ uint32_t swz128(int row, int u) {
    return (uint32_t)(row * 128 + ((u ^ (row & 7)) << 4));
}

// ---------------------------------------------------------------------------
// fp32 -> bf16 hi/lo split  (0=x, 1=qkv_w, 2=proj_w)
// ---------------------------------------------------------------------------
template <int WHICH>
__global__ void convert_split_exact(const float* __restrict__ in, int n2)
{
    __nv_bfloat162* hi;
    __nv_bfloat162* lo;
    if (WHICH == 0) { hi = (__nv_bfloat162*)g_xh;  lo = (__nv_bfloat162*)g_xl; }
    if (WHICH == 1) { hi = (__nv_bfloat162*)g_wqh; lo = (__nv_bfloat162*)g_wql; }
    if (WHICH == 2) { hi = (__nv_bfloat162*)g_wph; lo = (__nv_bfloat162*)g_wpl; }

    int i = blockIdx.x * blockDim.x + threadIdx.x;
    if (i < n2) {
        float2 v = ((const float2*)in)[i];
        __nv_bfloat16 hx = __float2bfloat16_rn(v.x);
        __nv_bfloat16 hy = __float2bfloat16_rn(v.y);
        __nv_bfloat162 h; h.x = hx; h.y = hy;
        hi[i] = h;
        __nv_bfloat162 l;
        l.x = __float2bfloat16_rn(v.x - __bfloat162float(hx));
        l.y = __float2bfloat16_rn(v.y - __bfloat162float(hy));
        lo[i] = l;
    }
}

// ---------------------------------------------------------------------------
// HMMA GEMM, 3-stage cp.async pipeline, swizzled 64B-pitch smem.
// CTA 128x128, BK=32, 8 warps (2M x 4N). 2 CTAs/SM.
// MODE 0 epilogue: Q (scaled) / K / V all fp16 into g_Qf/g_Kf/g_Vh.
// ---------------------------------------------------------------------------
#define OP_B    (128 * 64)
#define STAGE_B (4 * OP_B)
static constexpr int GEMM_SMEM = 3 * STAGE_B;  // 98304

template <int MODE>
__global__ void __launch_bounds__(256, 2) gemm_mma(
    const float* __restrict__ bias1, const float* __restrict__ bias2,
    float* __restrict__ out)
{
    constexpr int K = DIM;
    constexpr int NST = K / 32;       // 24

    extern __shared__ char smem[];
    const uint32_t sbase = smem_to_u32(smem);

    const __nv_bfloat16* Ah = (MODE == 0) ? g_xh : g_oh;
    const __nv_bfloat16* Al = (MODE == 0) ? g_xl : g_ol;
    const __nv_bfloat16* Wh = (MODE == 0) ? g_wqh : g_wph;
    const __nv_bfloat16* Wl = (MODE == 0) ? g_wql : g_wpl;
    const __nv_bfloat16* gsrc[4] = { Ah, Al, Wh, Wl };

    const int tid  = threadIdx.x;
    const int lane = tid & 31;
    const int wid  = tid >> 5;
    const int mw   = wid >> 2;
    const int nw   = wid & 3;
    const int m0   = blockIdx.y * 128;
    const int n0   = blockIdx.x * 128;

    const int T   = lane >> 3;
    const int la  = lane & 7;
    const int arow = ((T & 1) << 3) + la;
    const int au   = T >> 1;
    const int brow = ((T >> 1) << 3) + la;
    const int bu   = T & 1;
    const int aswz = (arow >> 1) & 3;
    const int bswz = (brow >> 1) & 3;

    float acc[4][4][4];
#pragma unroll
    for (int i = 0; i < 4; i++)
#pragma unroll
        for (int j = 0; j < 4; j++)
#pragma unroll
            for (int k = 0; k < 4; k++) acc[i][j][k] = 0.f;

    auto load_stage = [&](int kb) {
        const int kq = kb * 32;
        const uint32_t sb = sbase + (uint32_t)((kb % 3) * STAGE_B);
#pragma unroll
        for (int i = 0; i < 8; i++) {
            int c   = i * 256 + tid;
            int op  = c >> 9;
            int rem = c & 511;
            int row = rem >> 2;
            int u   = rem & 3;
            int grow = (op < 2) ? (m0 + row) : (n0 + row);
            const __nv_bfloat16* g = gsrc[op] + (size_t)grow * K + kq + u * 8;
            cp_async16(sb + (uint32_t)(op * OP_B)
                       + (uint32_t)(row * 64 + ((u ^ ((row >> 1) & 3)) << 4)), g);
        }
        cp_commit();
    };

    load_stage(0);
    load_stage(1);
    load_stage(2);

    for (int kb = 0; kb < NST; kb++) {
        if (kb + 2 < NST) cp_wait2();
        else if (kb + 1 < NST) cp_wait1();
        else cp_wait0();
        __syncthreads();

        const uint32_t sb  = sbase + (uint32_t)((kb % 3) * STAGE_B);
        const uint32_t bAh = sb;
        const uint32_t bAl = sb + OP_B;
        const uint32_t bWh = sb + 2 * OP_B;
        const uint32_t bWl = sb + 3 * OP_B;

#pragma unroll
        for (int kk = 0; kk < 2; kk++) {
            uint32_t ah[4][4], al[4][4], wh[2][4], wl[2][4];
            const int uA = 2 * kk + au;
            const int uB = 2 * kk + bu;
#pragma unroll
            for (int ma = 0; ma < 4; ma++) {
                int row = mw * 64 + ma * 16 + arow;
                uint32_t off = (uint32_t)(row * 64 + ((uA ^ aswz) << 4));
                ldsm_x4(ah[ma], bAh + off);
                ldsm_x4(al[ma], bAl + off);
            }
#pragma unroll
            for (int nb = 0; nb < 2; nb++) {
                int row = nw * 32 + nb * 16 + brow;
                uint32_t off = (uint32_t)(row * 64 + ((uB ^ bswz) << 4));
                ldsm_x4(wh[nb], bWh + off);
                ldsm_x4(wl[nb], bWl + off);
            }
#pragma unroll
            for (int ma = 0; ma < 4; ma++)
#pragma unroll
                for (int na = 0; na < 4; na++) {
                    const uint32_t* bh = &wh[na >> 1][(na & 1) * 2];
                    const uint32_t* bl = &wl[na >> 1][(na & 1) * 2];
                    mma_bf16(acc[ma][na], ah[ma], bh);
                    mma_bf16(acc[ma][na], ah[ma], bl);
                    mma_bf16(acc[ma][na], al[ma], bh);
                }
        }
        __syncthreads();
        if (kb + 3 < NST) load_stage(kb + 3);
    }

    const int qrow = lane >> 2;
    const int qcol = (lane & 3) << 1;

    if (MODE == 0) {
        const int sec = blockIdx.x / 6;            // 0=q 1=k 2=v
        const int nl0 = (blockIdx.x % 6) * 128;
        __half* dst = (sec == 0) ? g_Qf : ((sec == 1) ? g_Kf : g_Vh);
#pragma unroll
        for (int na = 0; na < 4; na++) {
            const int c = nl0 + nw * 32 + na * 8 + qcol;   // 0..767
            const int h = c >> 6, d = c & 63;
            float bx = 0.f, by = 0.f;
            if (sec == 0) { bx = bias1[c]; by = bias1[c + 1]; }
            if (sec == 2) { bx = bias2[c]; by = bias2[c + 1]; }
#pragma unroll
            for (int ma = 0; ma < 4; ma++) {
                const int mr = m0 + mw * 64 + ma * 16 + qrow;
#pragma unroll
                for (int half = 0; half < 2; half++) {
                    int m = mr + half * 8;
                    int b = m >> 11, t = m & 2047;
                    float vx = acc[ma][na][half * 2 + 0] + bx;
                    float vy = acc[ma][na][half * 2 + 1] + by;
                    if (sec == 0) { vx *= SCALE_F; vy *= SCALE_F; }
                    size_t off = ((((size_t)b * HEADS + h) * SEQ + t) << 6) + d;
                    *(__half2*)&dst[off] = __floats2half2_rn(vx, vy);
                }
            }
        }
    } else {
#pragma unroll
        for (int na = 0; na < 4; na++) {
            const int n = n0 + nw * 32 + na * 8 + qcol;
            const float bx = bias1[n], by = bias1[n + 1];
#pragma unroll
            for (int ma = 0; ma < 4; ma++) {
                const int mr = m0 + mw * 64 + ma * 16 + qrow;
#pragma unroll
                for (int half = 0; half < 2; half++) {
                    int m = mr + half * 8;
                    float2 v;
                    v.x = acc[ma][na][half * 2 + 0] + bx;
                    v.y = acc[ma][na][half * 2 + 1] + by;
                    *(float2*)&out[(size_t)m * DIM + n] = v;
                }
            }
        }
    }
}

// ---------------------------------------------------------------------------
// HMMA flash attention, fp16 QK + fp16 PV, 3-stage KV prefetch, 2 CTAs/SM.
// Br=128, Bc=64, 8 warps. smem: Q 16K at 0; KV stages (K,V) 3 x 16K.
// ---------------------------------------------------------------------------
#define AQ_B    (128 * 128)             // 16384 (Q fp16, 128 rows x 128B)
#define AKV_OP  (64 * 128)              // 8192 per KV operand
#define AKV_ST  (2 * AKV_OP)            // 16384 per stage
static constexpr int ATTN_SMEM = AQ_B + 3 * AKV_ST;  // 65536

__global__ void __launch_bounds__(256, 2) attn_mma()
{
    extern __shared__ char smem[];
    const uint32_t sbase = smem_to_u32(smem);
    const uint32_t kvbase = sbase + AQ_B;

    const int tid  = threadIdx.x;
    const int lane = tid & 31;
    const int w    = tid >> 5;
    const int qb   = blockIdx.x;      // 0..15
    const int bh   = blockIdx.y;      // 0..47

    const int T  = lane >> 3;
    const int la = lane & 7;
    const int arow = ((T & 1) << 3) + la;
    const int au   = T >> 1;
    const int brow = ((T >> 1) << 3) + la;
    const int bu   = T & 1;
    const int vrow = ((T & 1) << 3) + la;
    const int vu   = T >> 1;

    const size_t bh_off = (size_t)bh * SEQ * HDIM;

    // ---- stage Q: 128 rows x 8 units ----
    {
        const size_t q0 = bh_off + (size_t)qb * 128 * HDIM;
#pragma unroll
        for (int i = 0; i < 4; i++) {
            int c = i * 256 + tid;       // 0..1023
            int row = c >> 3;            // 0..127
            int u = c & 7;
            cp_async16(sbase + swz128(row, u), g_Qf + q0 + (size_t)row * HDIM + u * 8);
        }
        cp_commit();
    }

    // ---- KV prefetch: 2 ops x 64 rows x 8 units = 1024 chunks ----
    auto load_kv = [&](int it) {
        const size_t kv0 = bh_off + (size_t)it * 64 * HDIM;
        const uint32_t sb = kvbase + (uint32_t)((it % 3) * AKV_ST);
#pragma unroll
        for (int i = 0; i < 4; i++) {
            int c = i * 256 + tid;       // 0..1023
            int op = c >> 9;             // 0=K 1=V
            int rem = c & 511;
            int row = rem >> 3;          // 0..63
            int u = rem & 7;
            const __half* g = (op ? g_Vh : g_Kf) + kv0 + (size_t)row * HDIM + u * 8;
            cp_async16(sb + (uint32_t)(op * AKV_OP) + swz128(row, u), g);
        }
        cp_commit();
    };

    load_kv(0);
    load_kv(1);
    load_kv(2);

    cp_wait3();   // Q group done (3 KV groups pending)
    __syncthreads();

    uint32_t qf[4][4];
#pragma unroll
    for (int kk = 0; kk < 4; kk++) {
        int row = w * 16 + arow;
        ldsm_x4(qf[kk], sbase + swz128(row, 2 * kk + au));
    }

    float o[8][4];
#pragma unroll
    for (int n = 0; n < 8; n++)
#pragma unroll
        for (int k = 0; k < 4; k++) o[n][k] = 0.f;
    float mA = -1e30f, mB = -1e30f, lA = 0.f, lB = 0.f;

    const int NIT = SEQ / 64;   // 32
    for (int it = 0; it < NIT; it++) {
        if (it + 2 < NIT) cp_wait2();
        else if (it + 1 < NIT) cp_wait1();
        else cp_wait0();
        __syncthreads();

        const uint32_t sb = kvbase + (uint32_t)((it % 3) * AKV_ST);
        const uint32_t sK = sb;
        const uint32_t sV = sb + AKV_OP;

        // ---- S = Q K^T (fp16 single-pass) ----
        float s[8][4];
#pragma unroll
        for (int n = 0; n < 8; n++)
#pragma unroll
            for (int k = 0; k < 4; k++) s[n][k] = 0.f;

#pragma unroll
        for (int kk = 0; kk < 4; kk++) {
#pragma unroll
            for (int j = 0; j < 4; j++) {
                uint32_t kf[4];
                int row = j * 16 + brow;
                ldsm_x4(kf, sK + swz128(row, 2 * kk + bu));
                mma_f16(s[2 * j + 0], qf[kk], kf + 0);
                mma_f16(s[2 * j + 1], qf[kk], kf + 2);
            }
        }

        // ---- online softmax ----
        float mxA = -1e30f, mxB = -1e30f;
#pragma unroll
        for (int n = 0; n < 8; n++) {
            mxA = fmaxf(mxA, fmaxf(s[n][0], s[n][1]));
            mxB = fmaxf(mxB, fmaxf(s[n][2], s[n][3]));
        }
        mxA = fmaxf(mxA, __shfl_xor_sync(0xffffffffu, mxA, 1));
        mxA = fmaxf(mxA, __shfl_xor_sync(0xffffffffu, mxA, 2));
        mxB = fmaxf(mxB, __shfl_xor_sync(0xffffffffu, mxB, 1));
        mxB = fmaxf(mxB, __shfl_xor_sync(0xffffffffu, mxB, 2));

        float mAn = fmaxf(mA, mxA);
        float mBn = fmaxf(mB, mxB);
        float nmA = mAn * LOG2E_F;
        float nmB = mBn * LOG2E_F;
        float alphaA = ex2f(mA * LOG2E_F - nmA);
        float alphaB = ex2f(mB * LOG2E_F - nmB);
        mA = mAn; mB = mBn;

        float sumA = 0.f, sumB = 0.f;
        uint32_t pa[8], pb[8];
#pragma unroll
        for (int n = 0; n < 8; n++) {
            float p0 = ex2f(fmaf(s[n][0], LOG2E_F, -nmA));
            float p1 = ex2f(fmaf(s[n][1], LOG2E_F, -nmA));
            float p2 = ex2f(fmaf(s[n][2], LOG2E_F, -nmB));
            float p3 = ex2f(fmaf(s[n][3], LOG2E_F, -nmB));
            sumA += p0 + p1;
            sumB += p2 + p3;
            pa[n] = pack_f16x2(p0, p1);
            pb[n] = pack_f16x2(p2, p3);
        }
        sumA += __shfl_xor_sync(0xffffffffu, sumA, 1);
        sumA += __shfl_xor_sync(0xffffffffu, sumA, 2);
        sumB += __shfl_xor_sync(0xffffffffu, sumB, 1);
        sumB += __shfl_xor_sync(0xffffffffu, sumB, 2);
        lA = lA * alphaA + sumA;
        lB = lB * alphaB + sumB;

#pragma unroll
        for (int n = 0; n < 8; n++) {
            o[n][0] *= alphaA; o[n][1] *= alphaA;
            o[n][2] *= alphaB; o[n][3] *= alphaB;
        }

        // ---- O += P V (fp16, trans B-frags) ----
#pragma unroll
        for (int kk = 0; kk < 4; kk++) {
            uint32_t a[4] = { pa[2 * kk], pb[2 * kk], pa[2 * kk + 1], pb[2 * kk + 1] };
#pragma unroll
            for (int j = 0; j < 4; j++) {
                uint32_t vb[4];
                int row = kk * 16 + vrow;
                ldsm_x4_t(vb, sV + swz128(row, 2 * j + vu));
                mma_f16(o[2 * j + 0], a, vb + 0);
                mma_f16(o[2 * j + 1], a, vb + 2);
            }
        }

        __syncthreads();
        if (it + 3 < NIT) load_kv(it + 3);
    }

    // ---- epilogue: normalize + bf16 split -> g_oh / g_ol ----
    const int b = bh / HEADS;
    const int h = bh - b * HEADS;
    const float invA = 1.0f / lA;
    const float invB = 1.0f / lB;
    const int tA = qb * 128 + w * 16 + (lane >> 2);
    const int tB = tA + 8;
#pragma unroll
    for (int n = 0; n < 8; n++) {
        int c = h * 64 + n * 8 + ((lane & 3) << 1);
        size_t offA = ((size_t)b * SEQ + tA) * DIM + c;
        size_t offB = ((size_t)b * SEQ + tB) * DIM + c;
        float vx = o[n][0] * invA, vy = o[n][1] * invA;
        __nv_bfloat16 hx = __float2bfloat16_rn(vx);
        __nv_bfloat16 hy = __float2bfloat16_rn(vy);
        __nv_bfloat162 hv; hv.x = hx; hv.y = hy;
        __nv_bfloat162 lv;
        lv.x = __float2bfloat16_rn(vx - __bfloat162float(hx));
        lv.y = __float2bfloat16_rn(vy - __bfloat162float(hy));
        *(__nv_bfloat162*)&g_oh[offA] = hv;
        *(__nv_bfloat162*)&g_ol[offA] = lv;

        vx = o[n][2] * invB; vy = o[n][3] * invB;
        hx = __float2bfloat16_rn(vx); hy = __float2bfloat16_rn(vy);
        hv.x = hx; hv.y = hy;
        lv.x = __float2bfloat16_rn(vx - __bfloat162float(hx));
        lv.y = __float2bfloat16_rn(vy - __bfloat162float(hy));
        *(__nv_bfloat162*)&g_oh[offB] = hv;
        *(__nv_bfloat162*)&g_ol[offB] = lv;
    }
}

// ---------------------------------------------------------------------------
extern "C" void kernel_launch(void* const* d_in, const int* in_sizes, int n_in,
                              void* d_out, int out_size)
{
    (void)in_sizes; (void)n_in; (void)out_size;
    const float* x      = (const float*)d_in[0];
    const float* qkv_w  = (const float*)d_in[1];
    const float* q_bias = (const float*)d_in[2];
    const float* v_bias = (const float*)d_in[3];
    const float* proj_w = (const float*)d_in[4];
    const float* proj_b = (const float*)d_in[5];
    float* out = (float*)d_out;

    cudaFuncSetAttribute(gemm_mma<0>, cudaFuncAttributeMaxDynamicSharedMemorySize, GEMM_SMEM);
    cudaFuncSetAttribute(gemm_mma<1>, cudaFuncAttributeMaxDynamicSharedMemorySize, GEMM_SMEM);
    cudaFuncSetAttribute(attn_mma,    cudaFuncAttributeMaxDynamicSharedMemorySize, ATTN_SMEM);

    // 0) split fp32 -> bf16 hi/lo
    convert_split_exact<0><<<(BATCH * SEQ * DIM / 2 + 255) / 256, 256>>>(x, BATCH * SEQ * DIM / 2);
    convert_split_exact<1><<<(3 * DIM * DIM / 2 + 255) / 256, 256>>>(qkv_w, 3 * DIM * DIM / 2);
    convert_split_exact<2><<<(DIM * DIM / 2 + 255) / 256, 256>>>(proj_w, DIM * DIM / 2);

    // 1) QKV GEMM (HMMA, 3-term bf16) -> Q/K/V fp16
    gemm_mma<0><<<dim3(3 * DIM / 128, BATCH * SEQ / 128), 256, GEMM_SMEM>>>(
        q_bias, v_bias, nullptr);

    // 2) Flash attention (fp16 HMMA) -> split O bf16
    attn_mma<<<dim3(SEQ / 128, BATCH * HEADS), 256, ATTN_SMEM>>>();

    // 3) Projection GEMM (HMMA, 3-term bf16) + bias
    gemm_mma<1><<<dim3(DIM / 128, BATCH * SEQ / 128), 256, GEMM_SMEM>>>(
        proj_b, nullptr, out);
}

// round 8
// speedup vs baseline: 6.7579x; 1.3143x over previous
#include <cuda_runtime.h>
#include <cuda_bf16.h>
#include <cuda_fp16.h>
#include <cstdint>

#define BATCH 4
#define SEQ   2048
#define DIM   768
#define HEADS 12
#define HDIM  64
#define SCALE_F 0.125f   // 64^-0.5
#define LOG2E_F 1.4426950408889634f

// ---------------------------------------------------------------------------
// Scratch (allocation-free rule: __device__ globals)
// ---------------------------------------------------------------------------
static __device__ __half g_Qf[(size_t)BATCH * HEADS * SEQ * HDIM];
static __device__ __half g_Kf[(size_t)BATCH * HEADS * SEQ * HDIM];
static __device__ __half g_Vh[(size_t)BATCH * HEADS * SEQ * HDIM];

static __device__ __half g_xf[(size_t)BATCH * SEQ * DIM];
static __device__ __half g_wqf[(size_t)3 * DIM * DIM];

static __device__ __nv_bfloat16 g_oh[(size_t)BATCH * SEQ * DIM];
static __device__ __nv_bfloat16 g_ol[(size_t)BATCH * SEQ * DIM];
static __device__ __nv_bfloat16 g_wph[(size_t)DIM * DIM];
static __device__ __nv_bfloat16 g_wpl[(size_t)DIM * DIM];

// ---------------------------------------------------------------------------
// helpers
// ---------------------------------------------------------------------------
__device__ __forceinline__ uint32_t smem_to_u32(const void* p) {
    uint32_t a;
    asm("{ .reg .u64 t; cvta.to.shared.u64 t, %1; cvt.u32.u64 %0, t; }"
        : "=r"(a) : "l"(p));
    return a;
}
__device__ __forceinline__ void cp_async16(uint32_t saddr, const void* gaddr) {
    asm volatile("cp.async.cg.shared.global [%0], [%1], 16;"
                 :: "r"(saddr), "l"(gaddr));
}
__device__ __forceinline__ void cp_commit() {
    asm volatile("cp.async.commit_group;");
}
__device__ __forceinline__ void cp_wait0() {
    asm volatile("cp.async.wait_group 0;" ::: "memory");
}
__device__ __forceinline__ void cp_wait1() {
    asm volatile("cp.async.wait_group 1;" ::: "memory");
}
__device__ __forceinline__ void cp_wait2() {
    asm volatile("cp.async.wait_group 2;" ::: "memory");
}
__device__ __forceinline__ void cp_wait3() {
    asm volatile("cp.async.wait_group 3;" ::: "memory");
}
__device__ __forceinline__ void ldsm_x4(uint32_t* r, uint32_t addr) {
    asm volatile("ldmatrix.sync.aligned.m8n8.x4.shared.b16 {%0,%1,%2,%3}, [%4];"
                 : "=r"(r[0]), "=r"(r[1]), "=r"(r[2]), "=r"(r[3]) : "r"(addr));
}
__device__ __forceinline__ void ldsm_x4_t(uint32_t* r, uint32_t addr) {
    asm volatile("ldmatrix.sync.aligned.m8n8.x4.trans.shared.b16 {%0,%1,%2,%3}, [%4];"
                 : "=r"(r[0]), "=r"(r[1]), "=r"(r[2]), "=r"(r[3]) : "r"(addr));
}
__device__ __forceinline__ void mma_bf16(float* d, const uint32_t* a,
                                         const uint32_t* b) {
    asm volatile(
        "mma.sync.aligned.m16n8k16.row.col.f32.bf16.bf16.f32 "
        "{%0,%1,%2,%3}, {%4,%5,%6,%7}, {%8,%9}, {%0,%1,%2,%3};"
        : "+f"(d[0]), "+f"(d[1]), "+f"(d[2]), "+f"(d[3])
        : "r"(a[0]), "r"(a[1]), "r"(a[2]), "r"(a[3]), "r"(b[0]), "r"(b[1]));
}
__device__ __forceinline__ void mma_f16(float* d, const uint32_t* a,
                                        const uint32_t* b) {
    asm volatile(
        "mma.sync.aligned.m16n8k16.row.col.f32.f16.f16.f32 "
        "{%0,%1,%2,%3}, {%4,%5,%6,%7}, {%8,%9}, {%0,%1,%2,%3};"
        : "+f"(d[0]), "+f"(d[1]), "+f"(d[2]), "+f"(d[3])
        : "r"(a[0]), "r"(a[1]), "r"(a[2]), "r"(a[3]), "r"(b[0]), "r"(b[1]));
}
__device__ __forceinline__ float ex2f(float x) {
    float r;
    asm("ex2.approx.f32 %0, %1;" : "=f"(r) : "f"(x));
    return r;
}
__device__ __forceinline__ uint32_t pack_f16x2(float lo, float hi) {
    uint32_t r;
    asm("cvt.rn.f16x2.f32 %0, %1, %2;" : "=r"(r) : "f"(hi), "f"(lo));
    return r;
}
// 64B-pitch rows, XOR swizzle over 4x16B units
__device__ __forceinline__ uint32_t swz64(int row, int u) {
    return (uint32_t)(row * 64 + ((u ^ ((row >> 1) & 3)) << 4));
}
// 128B-pitch rows, XOR swizzle over 8x16B units
__device__ __forceinline__ uint32_t swz128(int row, int u) {
    return (uint32_t)(row * 128 + ((u ^ (row & 7)) << 4));
}

// ---------------------------------------------------------------------------
// converts
// ---------------------------------------------------------------------------
// fp32 -> fp16  (0=x, 1=qkv_w)
template <int WHICH>
__global__ void convert_f16(const float* __restrict__ in, int n2)
{
    __half2* dst = (WHICH == 0) ? (__half2*)g_xf : (__half2*)g_wqf;
    int i = blockIdx.x * blockDim.x + threadIdx.x;
    if (i < n2) {
        float2 v = ((const float2*)in)[i];
        dst[i] = __floats2half2_rn(v.x, v.y);
    }
}
// fp32 -> bf16 hi/lo split (proj_w)
__global__ void convert_split_w(const float* __restrict__ in, int n2)
{
    __nv_bfloat162* hi = (__nv_bfloat162*)g_wph;
    __nv_bfloat162* lo = (__nv_bfloat162*)g_wpl;
    int i = blockIdx.x * blockDim.x + threadIdx.x;
    if (i < n2) {
        float2 v = ((const float2*)in)[i];
        __nv_bfloat16 hx = __float2bfloat16_rn(v.x);
        __nv_bfloat16 hy = __float2bfloat16_rn(v.y);
        __nv_bfloat162 h; h.x = hx; h.y = hy;
        hi[i] = h;
        __nv_bfloat162 l;
        l.x = __float2bfloat16_rn(v.x - __bfloat162float(hx));
        l.y = __float2bfloat16_rn(v.y - __bfloat162float(hy));
        lo[i] = l;
    }
}

// ---------------------------------------------------------------------------
// QKV GEMM: single-pass fp16 HMMA, 3-stage pipeline, 2 CTAs/SM.
// CTA 128x128, BK=32, 8 warps (2M x 4N).
// Epilogue: Q(scaled)/K/V fp16 scatter with bias.
// ---------------------------------------------------------------------------
#define FOP_B    (128 * 64)           // 8192 per fp16 operand tile
#define FSTAGE_B (2 * FOP_B)          // 16384 per stage
static constexpr int GEMMF_SMEM = 3 * FSTAGE_B;  // 49152

__global__ void __launch_bounds__(256, 2) gemm_qkv_f16(
    const float* __restrict__ q_bias, const float* __restrict__ v_bias)
{
    constexpr int K = DIM;
    constexpr int NST = K / 32;       // 24

    extern __shared__ char smem[];
    const uint32_t sbase = smem_to_u32(smem);

    const int tid  = threadIdx.x;
    const int lane = tid & 31;
    const int wid  = tid >> 5;
    const int mw   = wid >> 2;
    const int nw   = wid & 3;
    const int m0   = blockIdx.y * 128;
    const int n0   = blockIdx.x * 128;

    const int T   = lane >> 3;
    const int la  = lane & 7;
    const int arow = ((T & 1) << 3) + la;
    const int au   = T >> 1;
    const int brow = ((T >> 1) << 3) + la;
    const int bu   = T & 1;
    const int aswz = (arow >> 1) & 3;
    const int bswz = (brow >> 1) & 3;

    float acc[4][4][4];
#pragma unroll
    for (int i = 0; i < 4; i++)
#pragma unroll
        for (int j = 0; j < 4; j++)
#pragma unroll
            for (int k = 0; k < 4; k++) acc[i][j][k] = 0.f;

    auto load_stage = [&](int kb) {
        const int kq = kb * 32;
        const uint32_t sb = sbase + (uint32_t)((kb % 3) * FSTAGE_B);
#pragma unroll
        for (int i = 0; i < 4; i++) {
            int c   = i * 256 + tid;      // 0..1023
            int op  = c >> 9;             // 0=A 1=W
            int rem = c & 511;
            int row = rem >> 2;
            int u   = rem & 3;
            const __half* g = op ? (g_wqf + (size_t)(n0 + row) * K + kq + u * 8)
                                 : (g_xf  + (size_t)(m0 + row) * K + kq + u * 8);
            cp_async16(sb + (uint32_t)(op * FOP_B) + swz64(row, u), g);
        }
        cp_commit();
    };

    load_stage(0);
    load_stage(1);
    load_stage(2);

    for (int kb = 0; kb < NST; kb++) {
        if (kb + 2 < NST) cp_wait2();
        else if (kb + 1 < NST) cp_wait1();
        else cp_wait0();
        __syncthreads();

        const uint32_t sb = sbase + (uint32_t)((kb % 3) * FSTAGE_B);
        const uint32_t bA = sb;
        const uint32_t bW = sb + FOP_B;

#pragma unroll
        for (int kk = 0; kk < 2; kk++) {
            uint32_t af[4][4], wf[2][4];
            const int uA = 2 * kk + au;
            const int uB = 2 * kk + bu;
#pragma unroll
            for (int ma = 0; ma < 4; ma++) {
                int row = mw * 64 + ma * 16 + arow;
                ldsm_x4(af[ma], bA + (uint32_t)(row * 64 + ((uA ^ aswz) << 4)));
            }
#pragma unroll
            for (int nb = 0; nb < 2; nb++) {
                int row = nw * 32 + nb * 16 + brow;
                ldsm_x4(wf[nb], bW + (uint32_t)(row * 64 + ((uB ^ bswz) << 4)));
            }
#pragma unroll
            for (int ma = 0; ma < 4; ma++)
#pragma unroll
                for (int na = 0; na < 4; na++)
                    mma_f16(acc[ma][na], af[ma], &wf[na >> 1][(na & 1) * 2]);
        }
        __syncthreads();
        if (kb + 3 < NST) load_stage(kb + 3);
    }

    const int qrow = lane >> 2;
    const int qcol = (lane & 3) << 1;
    const int sec = blockIdx.x / 6;            // 0=q 1=k 2=v
    const int nl0 = (blockIdx.x % 6) * 128;
    __half* dst = (sec == 0) ? g_Qf : ((sec == 1) ? g_Kf : g_Vh);
#pragma unroll
    for (int na = 0; na < 4; na++) {
        const int c = nl0 + nw * 32 + na * 8 + qcol;   // 0..767
        const int h = c >> 6, d = c & 63;
        float bx = 0.f, by = 0.f;
        if (sec == 0) { bx = q_bias[c]; by = q_bias[c + 1]; }
        if (sec == 2) { bx = v_bias[c]; by = v_bias[c + 1]; }
#pragma unroll
        for (int ma = 0; ma < 4; ma++) {
            const int mr = m0 + mw * 64 + ma * 16 + qrow;
#pragma unroll
            for (int half = 0; half < 2; half++) {
                int m = mr + half * 8;
                int b = m >> 11, t = m & 2047;
                float vx = acc[ma][na][half * 2 + 0] + bx;
                float vy = acc[ma][na][half * 2 + 1] + by;
                if (sec == 0) { vx *= SCALE_F; vy *= SCALE_F; }
                size_t off = ((((size_t)b * HEADS + h) * SEQ + t) << 6) + d;
                *(__half2*)&dst[off] = __floats2half2_rn(vx, vy);
            }
        }
    }
}

// ---------------------------------------------------------------------------
// Projection GEMM: 3-term bf16 split HMMA (error goes straight to output).
// A = g_oh/g_ol (written by attention), W = g_wph/g_wpl.
// ---------------------------------------------------------------------------
#define OP_B    (128 * 64)
#define STAGE_B (4 * OP_B)
static constexpr int GEMM_SMEM = 3 * STAGE_B;  // 98304

__global__ void __launch_bounds__(256, 2) gemm_proj(
    const float* __restrict__ bias1, float* __restrict__ out)
{
    constexpr int K = DIM;
    constexpr int NST = K / 32;       // 24

    extern __shared__ char smem[];
    const uint32_t sbase = smem_to_u32(smem);

    const __nv_bfloat16* gsrc[4] = { g_oh, g_ol, g_wph, g_wpl };

    const int tid  = threadIdx.x;
    const int lane = tid & 31;
    const int wid  = tid >> 5;
    const int mw   = wid >> 2;
    const int nw   = wid & 3;
    const int m0   = blockIdx.y * 128;
    const int n0   = blockIdx.x * 128;

    const int T   = lane >> 3;
    const int la  = lane & 7;
    const int arow = ((T & 1) << 3) + la;
    const int au   = T >> 1;
    const int brow = ((T >> 1) << 3) + la;
    const int bu   = T & 1;
    const int aswz = (arow >> 1) & 3;
    const int bswz = (brow >> 1) & 3;

    float acc[4][4][4];
#pragma unroll
    for (int i = 0; i < 4; i++)
#pragma unroll
        for (int j = 0; j < 4; j++)
#pragma unroll
            for (int k = 0; k < 4; k++) acc[i][j][k] = 0.f;

    auto load_stage = [&](int kb) {
        const int kq = kb * 32;
        const uint32_t sb = sbase + (uint32_t)((kb % 3) * STAGE_B);
#pragma unroll
        for (int i = 0; i < 8; i++) {
            int c   = i * 256 + tid;
            int op  = c >> 9;
            int rem = c & 511;
            int row = rem >> 2;
            int u   = rem & 3;
            int grow = (op < 2) ? (m0 + row) : (n0 + row);
            const __nv_bfloat16* g = gsrc[op] + (size_t)grow * K + kq + u * 8;
            cp_async16(sb + (uint32_t)(op * OP_B) + swz64(row, u), g);
        }
        cp_commit();
    };

    load_stage(0);
    load_stage(1);
    load_stage(2);

    for (int kb = 0; kb < NST; kb++) {
        if (kb + 2 < NST) cp_wait2();
        else if (kb + 1 < NST) cp_wait1();
        else cp_wait0();
        __syncthreads();

        const uint32_t sb  = sbase + (uint32_t)((kb % 3) * STAGE_B);
        const uint32_t bAh = sb;
        const uint32_t bAl = sb + OP_B;
        const uint32_t bWh = sb + 2 * OP_B;
        const uint32_t bWl = sb + 3 * OP_B;

#pragma unroll
        for (int kk = 0; kk < 2; kk++) {
            uint32_t ah[4][4], al[4][4], wh[2][4], wl[2][4];
            const int uA = 2 * kk + au;
            const int uB = 2 * kk + bu;
#pragma unroll
            for (int ma = 0; ma < 4; ma++) {
                int row = mw * 64 + ma * 16 + arow;
                uint32_t off = (uint32_t)(row * 64 + ((uA ^ aswz) << 4));
                ldsm_x4(ah[ma], bAh + off);
                ldsm_x4(al[ma], bAl + off);
            }
#pragma unroll
            for (int nb = 0; nb < 2; nb++) {
                int row = nw * 32 + nb * 16 + brow;
                uint32_t off = (uint32_t)(row * 64 + ((uB ^ bswz) << 4));
                ldsm_x4(wh[nb], bWh + off);
                ldsm_x4(wl[nb], bWl + off);
            }
#pragma unroll
            for (int ma = 0; ma < 4; ma++)
#pragma unroll
                for (int na = 0; na < 4; na++) {
                    const uint32_t* bh = &wh[na >> 1][(na & 1) * 2];
                    const uint32_t* bl = &wl[na >> 1][(na & 1) * 2];
                    mma_bf16(acc[ma][na], ah[ma], bh);
                    mma_bf16(acc[ma][na], ah[ma], bl);
                    mma_bf16(acc[ma][na], al[ma], bh);
                }
        }
        __syncthreads();
        if (kb + 3 < NST) load_stage(kb + 3);
    }

    const int qrow = lane >> 2;
    const int qcol = (lane & 3) << 1;
#pragma unroll
    for (int na = 0; na < 4; na++) {
        const int n = n0 + nw * 32 + na * 8 + qcol;
        const float bx = bias1[n], by = bias1[n + 1];
#pragma unroll
        for (int ma = 0; ma < 4; ma++) {
            const int mr = m0 + mw * 64 + ma * 16 + qrow;
#pragma unroll
            for (int half = 0; half < 2; half++) {
                int m = mr + half * 8;
                float2 v;
                v.x = acc[ma][na][half * 2 + 0] + bx;
                v.y = acc[ma][na][half * 2 + 1] + by;
                *(float2*)&out[(size_t)m * DIM + n] = v;
            }
        }
    }
}

// ---------------------------------------------------------------------------
// HMMA flash attention (round-7, unchanged): fp16 QK + fp16 PV, 3-stage KV.
// ---------------------------------------------------------------------------
#define AQ_B    (128 * 128)
#define AKV_OP  (64 * 128)
#define AKV_ST  (2 * AKV_OP)
static constexpr int ATTN_SMEM = AQ_B + 3 * AKV_ST;  // 65536

__global__ void __launch_bounds__(256, 2) attn_mma()
{
    extern __shared__ char smem[];
    const uint32_t sbase = smem_to_u32(smem);
    const uint32_t kvbase = sbase + AQ_B;

    const int tid  = threadIdx.x;
    const int lane = tid & 31;
    const int w    = tid >> 5;
    const int qb   = blockIdx.x;
    const int bh   = blockIdx.y;

    const int T  = lane >> 3;
    const int la = lane & 7;
    const int arow = ((T & 1) << 3) + la;
    const int au   = T >> 1;
    const int brow = ((T >> 1) << 3) + la;
    const int bu   = T & 1;
    const int vrow = ((T & 1) << 3) + la;
    const int vu   = T >> 1;

    const size_t bh_off = (size_t)bh * SEQ * HDIM;

    {
        const size_t q0 = bh_off + (size_t)qb * 128 * HDIM;
#pragma unroll
        for (int i = 0; i < 4; i++) {
            int c = i * 256 + tid;
            int row = c >> 3;
            int u = c & 7;
            cp_async16(sbase + swz128(row, u), g_Qf + q0 + (size_t)row * HDIM + u * 8);
        }
        cp_commit();
    }

    auto load_kv = [&](int it) {
        const size_t kv0 = bh_off + (size_t)it * 64 * HDIM;
        const uint32_t sb = kvbase + (uint32_t)((it % 3) * AKV_ST);
#pragma unroll
        for (int i = 0; i < 4; i++) {
            int c = i * 256 + tid;
            int op = c >> 9;
            int rem = c & 511;
            int row = rem >> 3;
            int u = rem & 7;
            const __half* g = (op ? g_Vh : g_Kf) + kv0 + (size_t)row * HDIM + u * 8;
            cp_async16(sb + (uint32_t)(op * AKV_OP) + swz128(row, u), g);
        }
        cp_commit();
    };

    load_kv(0);
    load_kv(1);
    load_kv(2);

    cp_wait3();
    __syncthreads();

    uint32_t qf[4][4];
#pragma unroll
    for (int kk = 0; kk < 4; kk++) {
        int row = w * 16 + arow;
        ldsm_x4(qf[kk], sbase + swz128(row, 2 * kk + au));
    }

    float o[8][4];
#pragma unroll
    for (int n = 0; n < 8; n++)
#pragma unroll
        for (int k = 0; k < 4; k++) o[n][k] = 0.f;
    float mA = -1e30f, mB = -1e30f, lA = 0.f, lB = 0.f;

    const int NIT = SEQ / 64;
    for (int it = 0; it < NIT; it++) {
        if (it + 2 < NIT) cp_wait2();
        else if (it + 1 < NIT) cp_wait1();
        else cp_wait0();
        __syncthreads();

        const uint32_t sb = kvbase + (uint32_t)((it % 3) * AKV_ST);
        const uint32_t sK = sb;
        const uint32_t sV = sb + AKV_OP;

        float s[8][4];
#pragma unroll
        for (int n = 0; n < 8; n++)
#pragma unroll
            for (int k = 0; k < 4; k++) s[n][k] = 0.f;

#pragma unroll
        for (int kk = 0; kk < 4; kk++) {
#pragma unroll
            for (int j = 0; j < 4; j++) {
                uint32_t kf[4];
                int row = j * 16 + brow;
                ldsm_x4(kf, sK + swz128(row, 2 * kk + bu));
                mma_f16(s[2 * j + 0], qf[kk], kf + 0);
                mma_f16(s[2 * j + 1], qf[kk], kf + 2);
            }
        }

        float mxA = -1e30f, mxB = -1e30f;
#pragma unroll
        for (int n = 0; n < 8; n++) {
            mxA = fmaxf(mxA, fmaxf(s[n][0], s[n][1]));
            mxB = fmaxf(mxB, fmaxf(s[n][2], s[n][3]));
        }
        mxA = fmaxf(mxA, __shfl_xor_sync(0xffffffffu, mxA, 1));
        mxA = fmaxf(mxA, __shfl_xor_sync(0xffffffffu, mxA, 2));
        mxB = fmaxf(mxB, __shfl_xor_sync(0xffffffffu, mxB, 1));
        mxB = fmaxf(mxB, __shfl_xor_sync(0xffffffffu, mxB, 2));

        float mAn = fmaxf(mA, mxA);
        float mBn = fmaxf(mB, mxB);
        float nmA = mAn * LOG2E_F;
        float nmB = mBn * LOG2E_F;
        float alphaA = ex2f(mA * LOG2E_F - nmA);
        float alphaB = ex2f(mB * LOG2E_F - nmB);
        mA = mAn; mB = mBn;

        float sumA = 0.f, sumB = 0.f;
        uint32_t pa[8], pb[8];
#pragma unroll
        for (int n = 0; n < 8; n++) {
            float p0 = ex2f(fmaf(s[n][0], LOG2E_F, -nmA));
            float p1 = ex2f(fmaf(s[n][1], LOG2E_F, -nmA));
            float p2 = ex2f(fmaf(s[n][2], LOG2E_F, -nmB));
            float p3 = ex2f(fmaf(s[n][3], LOG2E_F, -nmB));
            sumA += p0 + p1;
            sumB += p2 + p3;
            pa[n] = pack_f16x2(p0, p1);
            pb[n] = pack_f16x2(p2, p3);
        }
        sumA += __shfl_xor_sync(0xffffffffu, sumA, 1);
        sumA += __shfl_xor_sync(0xffffffffu, sumA, 2);
        sumB += __shfl_xor_sync(0xffffffffu, sumB, 1);
        sumB += __shfl_xor_sync(0xffffffffu, sumB, 2);
        lA = lA * alphaA + sumA;
        lB = lB * alphaB + sumB;

#pragma unroll
        for (int n = 0; n < 8; n++) {
            o[n][0] *= alphaA; o[n][1] *= alphaA;
            o[n][2] *= alphaB; o[n][3] *= alphaB;
        }

#pragma unroll
        for (int kk = 0; kk < 4; kk++) {
            uint32_t a[4] = { pa[2 * kk], pb[2 * kk], pa[2 * kk + 1], pb[2 * kk + 1] };
#pragma unroll
            for (int j = 0; j < 4; j++) {
                uint32_t vb[4];
                int row = kk * 16 + vrow;
                ldsm_x4_t(vb, sV + swz128(row, 2 * j + vu));
                mma_f16(o[2 * j + 0], a, vb + 0);
                mma_f16(o[2 * j + 1], a, vb + 2);
            }
        }

        __syncthreads();
        if (it + 3 < NIT) load_kv(it + 3);
    }

    const int b = bh / HEADS;
    const int h = bh - b * HEADS;
    const float invA = 1.0f / lA;
    const float invB = 1.0f / lB;
    const int tA = qb * 128 + w * 16 + (lane >> 2);
    const int tB = tA + 8;
#pragma unroll
    for (int n = 0; n < 8; n++) {
        int c = h * 64 + n * 8 + ((lane & 3) << 1);
        size_t offA = ((size_t)b * SEQ + tA) * DIM + c;
        size_t offB = ((size_t)b * SEQ + tB) * DIM + c;
        float vx = o[n][0] * invA, vy = o[n][1] * invA;
        __nv_bfloat16 hx = __float2bfloat16_rn(vx);
        __nv_bfloat16 hy = __float2bfloat16_rn(vy);
        __nv_bfloat162 hv; hv.x = hx; hv.y = hy;
        __nv_bfloat162 lv;
        lv.x = __float2bfloat16_rn(vx - __bfloat162float(hx));
        lv.y = __float2bfloat16_rn(vy - __bfloat162float(hy));
        *(__nv_bfloat162*)&g_oh[offA] = hv;
        *(__nv_bfloat162*)&g_ol[offA] = lv;

        vx = o[n][2] * invB; vy = o[n][3] * invB;
        hx = __float2bfloat16_rn(vx); hy = __float2bfloat16_rn(vy);
        hv.x = hx; hv.y = hy;
        lv.x = __float2bfloat16_rn(vx - __bfloat162float(hx));
        lv.y = __float2bfloat16_rn(vy - __bfloat162float(hy));
        *(__nv_bfloat162*)&g_oh[offB] = hv;
        *(__nv_bfloat162*)&g_ol[offB] = lv;
    }
}

// ---------------------------------------------------------------------------
extern "C" void kernel_launch(void* const* d_in, const int* in_sizes, int n_in,
                              void* d_out, int out_size)
{
    (void)in_sizes; (void)n_in; (void)out_size;
    const float* x      = (const float*)d_in[0];
    const float* qkv_w  = (const float*)d_in[1];
    const float* q_bias = (const float*)d_in[2];
    const float* v_bias = (const float*)d_in[3];
    const float* proj_w = (const float*)d_in[4];
    const float* proj_b = (const float*)d_in[5];
    float* out = (float*)d_out;

    cudaFuncSetAttribute(gemm_qkv_f16, cudaFuncAttributeMaxDynamicSharedMemorySize, GEMMF_SMEM);
    cudaFuncSetAttribute(gemm_proj,    cudaFuncAttributeMaxDynamicSharedMemorySize, GEMM_SMEM);
    cudaFuncSetAttribute(attn_mma,     cudaFuncAttributeMaxDynamicSharedMemorySize, ATTN_SMEM);

    // 0) converts
    convert_f16<0><<<(BATCH * SEQ * DIM / 2 + 255) / 256, 256>>>(x, BATCH * SEQ * DIM / 2);
    convert_f16<1><<<(3 * DIM * DIM / 2 + 255) / 256, 256>>>(qkv_w, 3 * DIM * DIM / 2);
    convert_split_w<<<(DIM * DIM / 2 + 255) / 256, 256>>>(proj_w, DIM * DIM / 2);

    // 1) QKV GEMM (fp16 HMMA) -> Q/K/V fp16
    gemm_qkv_f16<<<dim3(3 * DIM / 128, BATCH * SEQ / 128), 256, GEMMF_SMEM>>>(
        q_bias, v_bias);

    // 2) Flash attention (fp16 HMMA) -> split O bf16
    attn_mma<<<dim3(SEQ / 128, BATCH * HEADS), 256, ATTN_SMEM>>>();

    // 3) Projection GEMM (3-term bf16 HMMA) + bias
    gemm_proj<<<dim3(DIM / 128, BATCH * SEQ / 128), 256, GEMM_SMEM>>>(
        proj_b, out);
}